// round 4
// baseline (speedup 1.0000x reference)
#include <cuda_runtime.h>

#define NN 100000
#define EE 1600000
#define ETOT (EE + NN)
#define HH 4
#define CC 32
#define DIM 128
#define NEG_SLOPE 0.2f
#define BN_EPS 1e-5f

// ---------------- scratch (static device globals; no allocs allowed) -------
__device__ float g_h[(size_t)NN * DIM];     // x @ W            (51.2 MB)
__device__ float g_acc[(size_t)NN * DIM];   // unnormalized agg (51.2 MB)
__device__ float g_asrc[NN * HH];
__device__ float g_adst[NN * HH];
__device__ float g_s[NN * HH];              // sum of exp per (node, head)
__device__ float g_colsum[DIM];
__device__ float g_colsq[DIM];
__device__ float g_scale[DIM];
__device__ float g_shift[DIM];

// ---------------- 0. zero scratch ------------------------------------------
__global__ void zero_kernel() {
    int i = blockIdx.x * blockDim.x + threadIdx.x;      // covers NN*32 float4
    if (i < NN * DIM / 4) ((float4*)g_acc)[i] = make_float4(0.f, 0.f, 0.f, 0.f);
    if (i < NN * HH) g_s[i] = 0.f;
    if (i < DIM) { g_colsum[i] = 0.f; g_colsq[i] = 0.f; }
}

// ---------------- 1. h = x @ W, plus per-node attention logits -------------
// 256 threads, 32 nodes per block (4 per warp), W fully staged in SMEM.
__global__ void gemm_kernel(const float* __restrict__ x,
                            const float* __restrict__ W,
                            const float* __restrict__ att_s,
                            const float* __restrict__ att_d) {
    extern __shared__ float sm[];
    float* ws = sm;                 // 128*128 = 64 KB
    float* xs = sm + DIM * DIM;     // 32*128  = 16 KB
    const int tid = threadIdx.x;
    const int nb  = blockIdx.x * 32;

    for (int i = tid * 4; i < DIM * DIM; i += 256 * 4)
        *(float4*)&ws[i] = *(const float4*)&W[i];
    for (int i = tid * 4; i < 32 * DIM; i += 256 * 4)
        *(float4*)&xs[i] = *(const float4*)&x[(size_t)nb * DIM + i];
    __syncthreads();

    const int warp = tid >> 5, lane = tid & 31;
    float acc[4][4];
#pragma unroll
    for (int n = 0; n < 4; n++)
#pragma unroll
        for (int j = 0; j < 4; j++) acc[n][j] = 0.f;

    const float* xrow = &xs[(warp * 4) * DIM];
#pragma unroll 8
    for (int k = 0; k < DIM; k += 4) {
        float4 w0 = *(float4*)&ws[(k + 0) * DIM + lane * 4];
        float4 w1 = *(float4*)&ws[(k + 1) * DIM + lane * 4];
        float4 w2 = *(float4*)&ws[(k + 2) * DIM + lane * 4];
        float4 w3 = *(float4*)&ws[(k + 3) * DIM + lane * 4];
#pragma unroll
        for (int n = 0; n < 4; n++) {
            float4 xv = *(float4*)&xrow[n * DIM + k];
            acc[n][0] = fmaf(xv.x, w0.x, acc[n][0]);
            acc[n][1] = fmaf(xv.x, w0.y, acc[n][1]);
            acc[n][2] = fmaf(xv.x, w0.z, acc[n][2]);
            acc[n][3] = fmaf(xv.x, w0.w, acc[n][3]);
            acc[n][0] = fmaf(xv.y, w1.x, acc[n][0]);
            acc[n][1] = fmaf(xv.y, w1.y, acc[n][1]);
            acc[n][2] = fmaf(xv.y, w1.z, acc[n][2]);
            acc[n][3] = fmaf(xv.y, w1.w, acc[n][3]);
            acc[n][0] = fmaf(xv.z, w2.x, acc[n][0]);
            acc[n][1] = fmaf(xv.z, w2.y, acc[n][1]);
            acc[n][2] = fmaf(xv.z, w2.z, acc[n][2]);
            acc[n][3] = fmaf(xv.z, w2.w, acc[n][3]);
            acc[n][0] = fmaf(xv.w, w3.x, acc[n][0]);
            acc[n][1] = fmaf(xv.w, w3.y, acc[n][1]);
            acc[n][2] = fmaf(xv.w, w3.z, acc[n][2]);
            acc[n][3] = fmaf(xv.w, w3.w, acc[n][3]);
        }
    }

    // per-head attention logits; lane covers cols lane*4..lane*4+3 (one head)
    const int head = lane >> 3;
    const int cb   = (lane & 7) * 4;
    float4 av = *(const float4*)&att_s[head * CC + cb];
    float4 bv = *(const float4*)&att_d[head * CC + cb];
#pragma unroll
    for (int n = 0; n < 4; n++) {
        const int node = nb + warp * 4 + n;
        *(float4*)&g_h[(size_t)node * DIM + lane * 4] =
            make_float4(acc[n][0], acc[n][1], acc[n][2], acc[n][3]);
        float ps = acc[n][0]*av.x + acc[n][1]*av.y + acc[n][2]*av.z + acc[n][3]*av.w;
        float pd = acc[n][0]*bv.x + acc[n][1]*bv.y + acc[n][2]*bv.z + acc[n][3]*bv.w;
#pragma unroll
        for (int off = 4; off; off >>= 1) {
            ps += __shfl_down_sync(0xffffffffu, ps, off, 8);
            pd += __shfl_down_sync(0xffffffffu, pd, off, 8);
        }
        if ((lane & 7) == 0) {
            g_asrc[node * HH + head] = ps;
            g_adst[node * HH + head] = pd;
        }
    }
}

// ---------------- 2. weighted scatter-add, 8 edges per warp ----------------
// Softmax without max-shift: logits bounded (|l| <~ 6), exp(l)/sum(exp(l))
// is exact in fp32. edge_index int32 [2,E]; self-loops appended virtually.
__global__ void passB_kernel(const int* __restrict__ ei) {
    const int wid  = (blockIdx.x * blockDim.x + threadIdx.x) >> 5;
    const int lane = threadIdx.x & 31;
    const long long base = (long long)wid * 8;   // first of 8 edges
    if (base >= ETOT) return;

    // lanes 0-7 load src ids, lanes 8-15 load dst ids
    int v = 0;
    if (lane < 16) {
        long long id = base + (lane & 7);
        if (id < ETOT) {
            if (id < EE) v = (lane < 8) ? __ldg(&ei[id]) : __ldg(&ei[EE + id]);
            else         v = (int)(id - EE);     // self loop
        }
    }
    int src[8], dst[8];
#pragma unroll
    for (int e = 0; e < 8; e++) {
        src[e] = __shfl_sync(0xffffffffu, v, e);
        dst[e] = __shfl_sync(0xffffffffu, v, 8 + e);
    }

    // every lane owns (edge pe = lane>>2, head ph = lane&3)
    const int pe = lane >> 2, ph = lane & 3;
    float p = 0.f;
    if (base + pe < ETOT) {
        float l = __ldg(&g_asrc[src[pe] * HH + ph]) +
                  __ldg(&g_adst[dst[pe] * HH + ph]);
        l = l > 0.f ? l : NEG_SLOPE * l;
        p = __expf(l);
        atomicAdd(&g_s[dst[pe] * HH + ph], p);
    }

    // 8 independent row gathers back-to-back (MLP = 8)
    float4 hv[8];
#pragma unroll
    for (int e = 0; e < 8; e++)
        hv[e] = *(const float4*)&g_h[(size_t)src[e] * DIM + lane * 4];

    const int myh = lane >> 3;                // head for this lane's columns
#pragma unroll
    for (int e = 0; e < 8; e++) {
        if (base + e < ETOT) {                // warp-uniform predicate
            float pw = __shfl_sync(0xffffffffu, p, e * 4 + myh);
            float* dp = &g_acc[(size_t)dst[e] * DIM + lane * 4];
            asm volatile("red.global.add.v4.f32 [%0], {%1, %2, %3, %4};"
                         :: "l"(dp), "f"(hv[e].x * pw), "f"(hv[e].y * pw),
                            "f"(hv[e].z * pw), "f"(hv[e].w * pw)
                         : "memory");
        }
    }
}

// ---------------- 3. BN column stats (read-only; no write-back) ------------
// one warp per node row; lane -> channel quad. Block-reduce in smem.
#define PC_WARPS 8
#define PC_NODES 32
__global__ void passC_kernel(const float* __restrict__ bias) {
    __shared__ float4 s_sum[PC_WARPS * 32];
    __shared__ float4 s_sq [PC_WARPS * 32];
    const int warp = threadIdx.x >> 5, lane = threadIdx.x & 31;
    const int head = lane >> 3;
    const float4 bv = *(const float4*)&bias[lane * 4];

    float4 sum = make_float4(0.f, 0.f, 0.f, 0.f);
    float4 sq  = make_float4(0.f, 0.f, 0.f, 0.f);
    const int node0 = (blockIdx.x * PC_WARPS + warp) * PC_NODES;
#pragma unroll 4
    for (int i = 0; i < PC_NODES; i++) {
        int node = node0 + i;
        if (node >= NN) break;
        float r = 1.f / (__ldg(&g_s[node * HH + head]) + 1e-16f);
        float4 a = *(const float4*)&g_acc[(size_t)node * DIM + lane * 4];
        float vx = fmaf(a.x, r, bv.x), vy = fmaf(a.y, r, bv.y);
        float vz = fmaf(a.z, r, bv.z), vw = fmaf(a.w, r, bv.w);
        sum.x += vx; sum.y += vy; sum.z += vz; sum.w += vw;
        sq.x = fmaf(vx, vx, sq.x); sq.y = fmaf(vy, vy, sq.y);
        sq.z = fmaf(vz, vz, sq.z); sq.w = fmaf(vw, vw, sq.w);
    }
    s_sum[warp * 32 + lane] = sum;
    s_sq [warp * 32 + lane] = sq;
    __syncthreads();
    if (warp == 0) {
#pragma unroll
        for (int w = 1; w < PC_WARPS; w++) {
            float4 a = s_sum[w * 32 + lane], b = s_sq[w * 32 + lane];
            sum.x += a.x; sum.y += a.y; sum.z += a.z; sum.w += a.w;
            sq.x  += b.x; sq.y  += b.y; sq.z  += b.z; sq.w  += b.w;
        }
        atomicAdd(&g_colsum[lane * 4 + 0], sum.x);
        atomicAdd(&g_colsum[lane * 4 + 1], sum.y);
        atomicAdd(&g_colsum[lane * 4 + 2], sum.z);
        atomicAdd(&g_colsum[lane * 4 + 3], sum.w);
        atomicAdd(&g_colsq[lane * 4 + 0], sq.x);
        atomicAdd(&g_colsq[lane * 4 + 1], sq.y);
        atomicAdd(&g_colsq[lane * 4 + 2], sq.z);
        atomicAdd(&g_colsq[lane * 4 + 3], sq.w);
    }
}

// ---------------- 4. fold BN stats into scale/shift -------------------------
__global__ void bn_kernel(const float* __restrict__ gamma,
                          const float* __restrict__ beta) {
    int c = threadIdx.x;
    float mean = g_colsum[c] * (1.f / NN);
    float var  = g_colsq[c] * (1.f / NN) - mean * mean;
    float sc   = gamma[c] * rsqrtf(var + BN_EPS);
    g_scale[c] = sc;
    g_shift[c] = beta[c] - mean * sc;
}

// ---------------- 5. normalize + bias + BN + residual + ReLU ---------------
__global__ void final_kernel(const float* __restrict__ x,
                             const float* __restrict__ bias,
                             float* __restrict__ out) {
    int i = blockIdx.x * blockDim.x + threadIdx.x;   // float4 index
    if (i >= NN * DIM / 4) return;
    int node = i >> 5, cq = i & 31, cb = cq * 4, head = cq >> 3;
    float r = 1.f / (__ldg(&g_s[node * HH + head]) + 1e-16f);
    float4 a  = ((const float4*)g_acc)[i];
    float4 xv = ((const float4*)x)[i];
    float4 bv = *(const float4*)&bias[cb];
    float4 sc = *(const float4*)&g_scale[cb];
    float4 sh = *(const float4*)&g_shift[cb];
    float4 o;
    o.x = fmaxf(fmaf(sc.x, fmaf(a.x, r, bv.x), sh.x) + xv.x, 0.f);
    o.y = fmaxf(fmaf(sc.y, fmaf(a.y, r, bv.y), sh.y) + xv.y, 0.f);
    o.z = fmaxf(fmaf(sc.z, fmaf(a.z, r, bv.z), sh.z) + xv.z, 0.f);
    o.w = fmaxf(fmaf(sc.w, fmaf(a.w, r, bv.w), sh.w) + xv.w, 0.f);
    ((float4*)out)[i] = o;
}

// ---------------- launch ----------------------------------------------------
extern "C" void kernel_launch(void* const* d_in, const int* in_sizes, int n_in,
                              void* d_out, int out_size) {
    const float* x     = (const float*)d_in[0];
    const int*   ei    = (const int*)d_in[1];      // int32 [2, E]
    const float* W     = (const float*)d_in[2];
    const float* att_s = (const float*)d_in[3];
    const float* att_d = (const float*)d_in[4];
    const float* bias  = (const float*)d_in[5];
    const float* gamma = (const float*)d_in[6];
    const float* beta  = (const float*)d_in[7];
    float*       out   = (float*)d_out;

    const int gemm_smem = (DIM * DIM + 32 * DIM) * sizeof(float);  // 80 KB
    cudaFuncSetAttribute(gemm_kernel, cudaFuncAttributeMaxDynamicSharedMemorySize,
                         gemm_smem);

    zero_kernel<<<(NN * 32 + 255) / 256, 256>>>();
    gemm_kernel<<<NN / 32, 256, gemm_smem>>>(x, W, att_s, att_d);
    // 8 edges/warp, 8 warps/block: ceil(ETOT/64) blocks
    passB_kernel<<<(ETOT + 63) / 64, 256>>>(ei);
    // one warp per node, 32 nodes/warp, 8 warps/block
    passC_kernel<<<(NN + PC_WARPS * PC_NODES - 1) / (PC_WARPS * PC_NODES), 256>>>(bias);
    bn_kernel<<<1, 128>>>(gamma, beta);
    final_kernel<<<(NN * 32 + 255) / 256, 256>>>(x, bias, out);
}

// round 5
// speedup vs baseline: 1.0470x; 1.0470x over previous
#include <cuda_runtime.h>

#define NN 100000
#define EE 1600000
#define ETOT (EE + NN)
#define HH 4
#define CC 32
#define DIM 128
#define NEG_SLOPE 0.2f
#define BN_EPS 1e-5f

// ---------------- scratch (static device globals; no allocs allowed) -------
__device__ float g_h[(size_t)NN * DIM];     // x @ W            (51.2 MB)
__device__ float g_acc[(size_t)NN * DIM];   // unnormalized agg (51.2 MB)
__device__ float g_asrc[NN * HH];
__device__ float g_adst[NN * HH];
__device__ float g_s[NN * HH];              // sum of exp per (node, head)
__device__ float g_colsum[DIM];
__device__ float g_colsq[DIM];
__device__ float g_scale[DIM];
__device__ float g_shift[DIM];

// ---------------- 0. zero small scratch (g_acc zeroed inside gemm) ---------
__global__ void zero_kernel() {
    int i = blockIdx.x * blockDim.x + threadIdx.x;
    if (i < NN * HH) g_s[i] = 0.f;
    if (i < DIM) { g_colsum[i] = 0.f; g_colsq[i] = 0.f; }
}

// ---------------- 1. h = x @ W, attention logits, zero g_acc ---------------
// 256 threads, 32 nodes per block (4 per warp), W fully staged in SMEM.
__global__ void gemm_kernel(const float* __restrict__ x,
                            const float* __restrict__ W,
                            const float* __restrict__ att_s,
                            const float* __restrict__ att_d) {
    extern __shared__ float sm[];
    float* ws = sm;                 // 128*128 = 64 KB
    float* xs = sm + DIM * DIM;     // 32*128  = 16 KB
    const int tid = threadIdx.x;
    const int nb  = blockIdx.x * 32;

    for (int i = tid * 4; i < DIM * DIM; i += 256 * 4)
        *(float4*)&ws[i] = *(const float4*)&W[i];
    for (int i = tid * 4; i < 32 * DIM; i += 256 * 4)
        *(float4*)&xs[i] = *(const float4*)&x[(size_t)nb * DIM + i];

    // zero this block's slice of g_acc while waiting (DRAM is idle here)
    const float4 z4 = make_float4(0.f, 0.f, 0.f, 0.f);
    for (int i = tid; i < 32 * DIM / 4; i += 256)
        ((float4*)&g_acc[(size_t)nb * DIM])[i] = z4;
    __syncthreads();

    const int warp = tid >> 5, lane = tid & 31;
    float acc[4][4];
#pragma unroll
    for (int n = 0; n < 4; n++)
#pragma unroll
        for (int j = 0; j < 4; j++) acc[n][j] = 0.f;

    const float* xrow = &xs[(warp * 4) * DIM];
#pragma unroll 8
    for (int k = 0; k < DIM; k += 4) {
        float4 w0 = *(float4*)&ws[(k + 0) * DIM + lane * 4];
        float4 w1 = *(float4*)&ws[(k + 1) * DIM + lane * 4];
        float4 w2 = *(float4*)&ws[(k + 2) * DIM + lane * 4];
        float4 w3 = *(float4*)&ws[(k + 3) * DIM + lane * 4];
#pragma unroll
        for (int n = 0; n < 4; n++) {
            float4 xv = *(float4*)&xrow[n * DIM + k];
            acc[n][0] = fmaf(xv.x, w0.x, acc[n][0]);
            acc[n][1] = fmaf(xv.x, w0.y, acc[n][1]);
            acc[n][2] = fmaf(xv.x, w0.z, acc[n][2]);
            acc[n][3] = fmaf(xv.x, w0.w, acc[n][3]);
            acc[n][0] = fmaf(xv.y, w1.x, acc[n][0]);
            acc[n][1] = fmaf(xv.y, w1.y, acc[n][1]);
            acc[n][2] = fmaf(xv.y, w1.z, acc[n][2]);
            acc[n][3] = fmaf(xv.y, w1.w, acc[n][3]);
            acc[n][0] = fmaf(xv.z, w2.x, acc[n][0]);
            acc[n][1] = fmaf(xv.z, w2.y, acc[n][1]);
            acc[n][2] = fmaf(xv.z, w2.z, acc[n][2]);
            acc[n][3] = fmaf(xv.z, w2.w, acc[n][3]);
            acc[n][0] = fmaf(xv.w, w3.x, acc[n][0]);
            acc[n][1] = fmaf(xv.w, w3.y, acc[n][1]);
            acc[n][2] = fmaf(xv.w, w3.z, acc[n][2]);
            acc[n][3] = fmaf(xv.w, w3.w, acc[n][3]);
        }
    }

    // per-head attention logits; lane covers cols lane*4..lane*4+3 (one head)
    const int head = lane >> 3;
    const int cb   = (lane & 7) * 4;
    float4 av = *(const float4*)&att_s[head * CC + cb];
    float4 bv = *(const float4*)&att_d[head * CC + cb];
#pragma unroll
    for (int n = 0; n < 4; n++) {
        const int node = nb + warp * 4 + n;
        *(float4*)&g_h[(size_t)node * DIM + lane * 4] =
            make_float4(acc[n][0], acc[n][1], acc[n][2], acc[n][3]);
        float ps = acc[n][0]*av.x + acc[n][1]*av.y + acc[n][2]*av.z + acc[n][3]*av.w;
        float pd = acc[n][0]*bv.x + acc[n][1]*bv.y + acc[n][2]*bv.z + acc[n][3]*bv.w;
#pragma unroll
        for (int off = 4; off; off >>= 1) {
            ps += __shfl_down_sync(0xffffffffu, ps, off, 8);
            pd += __shfl_down_sync(0xffffffffu, pd, off, 8);
        }
        if ((lane & 7) == 0) {
            g_asrc[node * HH + head] = ps;
            g_adst[node * HH + head] = pd;
        }
    }
}

// ---------------- 2. weighted scatter-add, 4 edges per warp ----------------
// Softmax without max-shift: logits bounded (|l| <~ 6), exp(l)/sum(exp(l))
// is exact in fp32. edge_index int32 [2,E]; self-loops appended virtually.
__global__ void passB_kernel(const int* __restrict__ ei) {
    const int wid  = (blockIdx.x * blockDim.x + threadIdx.x) >> 5;  // warp id
    const int lane = threadIdx.x & 31;
    const int base = wid * 4;                 // first of 4 edges (< ETOT)

    // lanes 0-3 load src[e], lanes 4-7 load dst[e]; self-loop for id >= EE
    int v = 0;
    if (lane < 8) {
        int id = base + (lane & 3);
        if (lane < 4) v = (id < EE) ? __ldg(&ei[id])      : id - EE;
        else          v = (id < EE) ? __ldg(&ei[EE + id]) : id - EE;
    }
    int src[4], dst[4];
#pragma unroll
    for (int e = 0; e < 4; e++) {
        src[e] = __shfl_sync(0xffffffffu, v, e);
        dst[e] = __shfl_sync(0xffffffffu, v, 4 + e);
    }

    // lanes 0-15 own (e = lane>>2, h = lane&3); 16-31 duplicate harmlessly
    const int pe = (lane >> 2) & 3, ph = lane & 3;
    float l = __ldg(&g_asrc[src[pe] * HH + ph]) + __ldg(&g_adst[dst[pe] * HH + ph]);
    l = l > 0.f ? l : NEG_SLOPE * l;
    float p = __expf(l);
    if (lane < 16) atomicAdd(&g_s[dst[pe] * HH + ph], p);

    // 4 independent row gathers issued back-to-back (MLP = 4)
    float4 hv[4];
#pragma unroll
    for (int e = 0; e < 4; e++)
        hv[e] = *(const float4*)&g_h[(size_t)src[e] * DIM + lane * 4];

    const int myh = lane >> 3;                // head for this lane's columns
#pragma unroll
    for (int e = 0; e < 4; e++) {
        float pw = __shfl_sync(0xffffffffu, p, e * 4 + myh);
        float* dp = &g_acc[(size_t)dst[e] * DIM + lane * 4];
        asm volatile("red.global.add.v4.f32 [%0], {%1, %2, %3, %4};"
                     :: "l"(dp), "f"(hv[e].x * pw), "f"(hv[e].y * pw),
                        "f"(hv[e].z * pw), "f"(hv[e].w * pw)
                     : "memory");
    }
}

// ---------------- 3. BN column stats (read-only; no write-back) ------------
// one warp per node row; lane -> channel quad. Block-reduce in smem.
#define PC_WARPS 8
#define PC_NODES 32
__global__ void passC_kernel(const float* __restrict__ bias) {
    __shared__ float4 s_sum[PC_WARPS * 32];
    __shared__ float4 s_sq [PC_WARPS * 32];
    const int warp = threadIdx.x >> 5, lane = threadIdx.x & 31;
    const int head = lane >> 3;
    const float4 bv = *(const float4*)&bias[lane * 4];

    float4 sum = make_float4(0.f, 0.f, 0.f, 0.f);
    float4 sq  = make_float4(0.f, 0.f, 0.f, 0.f);
    const int node0 = (blockIdx.x * PC_WARPS + warp) * PC_NODES;
#pragma unroll 4
    for (int i = 0; i < PC_NODES; i++) {
        int node = node0 + i;
        if (node >= NN) break;
        float r = 1.f / (__ldg(&g_s[node * HH + head]) + 1e-16f);
        float4 a = *(const float4*)&g_acc[(size_t)node * DIM + lane * 4];
        float vx = fmaf(a.x, r, bv.x), vy = fmaf(a.y, r, bv.y);
        float vz = fmaf(a.z, r, bv.z), vw = fmaf(a.w, r, bv.w);
        sum.x += vx; sum.y += vy; sum.z += vz; sum.w += vw;
        sq.x = fmaf(vx, vx, sq.x); sq.y = fmaf(vy, vy, sq.y);
        sq.z = fmaf(vz, vz, sq.z); sq.w = fmaf(vw, vw, sq.w);
    }
    s_sum[warp * 32 + lane] = sum;
    s_sq [warp * 32 + lane] = sq;
    __syncthreads();
    if (warp == 0) {
#pragma unroll
        for (int w = 1; w < PC_WARPS; w++) {
            float4 a = s_sum[w * 32 + lane], b = s_sq[w * 32 + lane];
            sum.x += a.x; sum.y += a.y; sum.z += a.z; sum.w += a.w;
            sq.x  += b.x; sq.y  += b.y; sq.z  += b.z; sq.w  += b.w;
        }
        atomicAdd(&g_colsum[lane * 4 + 0], sum.x);
        atomicAdd(&g_colsum[lane * 4 + 1], sum.y);
        atomicAdd(&g_colsum[lane * 4 + 2], sum.z);
        atomicAdd(&g_colsum[lane * 4 + 3], sum.w);
        atomicAdd(&g_colsq[lane * 4 + 0], sq.x);
        atomicAdd(&g_colsq[lane * 4 + 1], sq.y);
        atomicAdd(&g_colsq[lane * 4 + 2], sq.z);
        atomicAdd(&g_colsq[lane * 4 + 3], sq.w);
    }
}

// ---------------- 4. fold BN stats into scale/shift -------------------------
__global__ void bn_kernel(const float* __restrict__ gamma,
                          const float* __restrict__ beta) {
    int c = threadIdx.x;
    float mean = g_colsum[c] * (1.f / NN);
    float var  = g_colsq[c] * (1.f / NN) - mean * mean;
    float sc   = gamma[c] * rsqrtf(var + BN_EPS);
    g_scale[c] = sc;
    g_shift[c] = beta[c] - mean * sc;
}

// ---------------- 5. normalize + bias + BN + residual + ReLU ---------------
__global__ void final_kernel(const float* __restrict__ x,
                             const float* __restrict__ bias,
                             float* __restrict__ out) {
    int i = blockIdx.x * blockDim.x + threadIdx.x;   // float4 index
    if (i >= NN * DIM / 4) return;
    int node = i >> 5, cq = i & 31, cb = cq * 4, head = cq >> 3;
    float r = 1.f / (__ldg(&g_s[node * HH + head]) + 1e-16f);
    float4 a  = ((const float4*)g_acc)[i];
    float4 xv = ((const float4*)x)[i];
    float4 bv = *(const float4*)&bias[cb];
    float4 sc = *(const float4*)&g_scale[cb];
    float4 sh = *(const float4*)&g_shift[cb];
    float4 o;
    o.x = fmaxf(fmaf(sc.x, fmaf(a.x, r, bv.x), sh.x) + xv.x, 0.f);
    o.y = fmaxf(fmaf(sc.y, fmaf(a.y, r, bv.y), sh.y) + xv.y, 0.f);
    o.z = fmaxf(fmaf(sc.z, fmaf(a.z, r, bv.z), sh.z) + xv.z, 0.f);
    o.w = fmaxf(fmaf(sc.w, fmaf(a.w, r, bv.w), sh.w) + xv.w, 0.f);
    ((float4*)out)[i] = o;
}

// ---------------- launch ----------------------------------------------------
extern "C" void kernel_launch(void* const* d_in, const int* in_sizes, int n_in,
                              void* d_out, int out_size) {
    const float* x     = (const float*)d_in[0];
    const int*   ei    = (const int*)d_in[1];      // int32 [2, E]
    const float* W     = (const float*)d_in[2];
    const float* att_s = (const float*)d_in[3];
    const float* att_d = (const float*)d_in[4];
    const float* bias  = (const float*)d_in[5];
    const float* gamma = (const float*)d_in[6];
    const float* beta  = (const float*)d_in[7];
    float*       out   = (float*)d_out;

    const int gemm_smem = (DIM * DIM + 32 * DIM) * sizeof(float);  // 80 KB
    cudaFuncSetAttribute(gemm_kernel, cudaFuncAttributeMaxDynamicSharedMemorySize,
                         gemm_smem);

    zero_kernel<<<(NN * HH + 255) / 256, 256>>>();
    gemm_kernel<<<NN / 32, 256, gemm_smem>>>(x, W, att_s, att_d);
    // 4 edges per warp, 8 warps per block: ETOT/4/8 = 53125 blocks exactly
    passB_kernel<<<ETOT / 4 / 8, 256>>>(ei);
    passC_kernel<<<(NN + PC_WARPS * PC_NODES - 1) / (PC_WARPS * PC_NODES), 256>>>(bias);
    bn_kernel<<<1, 128>>>(gamma, beta);
    final_kernel<<<(NN * 32 + 255) / 256, 256>>>(x, bias, out);
}

// round 6
// speedup vs baseline: 1.0541x; 1.0068x over previous
#include <cuda_runtime.h>
#include <cuda_fp16.h>

#define NN 100000
#define EE 1600000
#define ETOT (EE + NN)
#define HH 4
#define CC 32
#define DIM 128
#define NEG_SLOPE 0.2f
#define BN_EPS 1e-5f

// ---------------- scratch (static device globals; no allocs allowed) -------
__device__ __half2 g_h2[(size_t)NN * (DIM / 2)];  // x @ W in fp16 (25.6 MB)
__device__ float   g_acc[(size_t)NN * DIM];       // unnormalized agg (51.2 MB)
__device__ float   g_asrc[NN * HH];
__device__ float   g_adst[NN * HH];
__device__ float   g_s[NN * HH];                  // sum of exp per (node, head)
__device__ float   g_colsum[DIM];
__device__ float   g_colsq[DIM];
__device__ float   g_scale[DIM];
__device__ float   g_shift[DIM];

// ---------------- 0. zero small scratch (g_acc zeroed inside gemm) ---------
__global__ void zero_kernel() {
    int i = blockIdx.x * blockDim.x + threadIdx.x;
    if (i < NN * HH) g_s[i] = 0.f;
    if (i < DIM) { g_colsum[i] = 0.f; g_colsq[i] = 0.f; }
}

// ---------------- 1. h = x @ W (fp32 math, fp16 store), logits, zero g_acc -
// 256 threads, 32 nodes per block (4 per warp), W fully staged in SMEM.
__global__ void gemm_kernel(const float* __restrict__ x,
                            const float* __restrict__ W,
                            const float* __restrict__ att_s,
                            const float* __restrict__ att_d) {
    extern __shared__ float sm[];
    float* ws = sm;                 // 128*128 = 64 KB
    float* xs = sm + DIM * DIM;     // 32*128  = 16 KB
    const int tid = threadIdx.x;
    const int nb  = blockIdx.x * 32;

    for (int i = tid * 4; i < DIM * DIM; i += 256 * 4)
        *(float4*)&ws[i] = *(const float4*)&W[i];
    for (int i = tid * 4; i < 32 * DIM; i += 256 * 4)
        *(float4*)&xs[i] = *(const float4*)&x[(size_t)nb * DIM + i];

    // zero this block's slice of g_acc while waiting (DRAM is idle here)
    const float4 z4 = make_float4(0.f, 0.f, 0.f, 0.f);
    for (int i = tid; i < 32 * DIM / 4; i += 256)
        ((float4*)&g_acc[(size_t)nb * DIM])[i] = z4;
    __syncthreads();

    const int warp = tid >> 5, lane = tid & 31;
    float acc[4][4];
#pragma unroll
    for (int n = 0; n < 4; n++)
#pragma unroll
        for (int j = 0; j < 4; j++) acc[n][j] = 0.f;

    const float* xrow = &xs[(warp * 4) * DIM];
#pragma unroll 8
    for (int k = 0; k < DIM; k += 4) {
        float4 w0 = *(float4*)&ws[(k + 0) * DIM + lane * 4];
        float4 w1 = *(float4*)&ws[(k + 1) * DIM + lane * 4];
        float4 w2 = *(float4*)&ws[(k + 2) * DIM + lane * 4];
        float4 w3 = *(float4*)&ws[(k + 3) * DIM + lane * 4];
#pragma unroll
        for (int n = 0; n < 4; n++) {
            float4 xv = *(float4*)&xrow[n * DIM + k];
            acc[n][0] = fmaf(xv.x, w0.x, acc[n][0]);
            acc[n][1] = fmaf(xv.x, w0.y, acc[n][1]);
            acc[n][2] = fmaf(xv.x, w0.z, acc[n][2]);
            acc[n][3] = fmaf(xv.x, w0.w, acc[n][3]);
            acc[n][0] = fmaf(xv.y, w1.x, acc[n][0]);
            acc[n][1] = fmaf(xv.y, w1.y, acc[n][1]);
            acc[n][2] = fmaf(xv.y, w1.z, acc[n][2]);
            acc[n][3] = fmaf(xv.y, w1.w, acc[n][3]);
            acc[n][0] = fmaf(xv.z, w2.x, acc[n][0]);
            acc[n][1] = fmaf(xv.z, w2.y, acc[n][1]);
            acc[n][2] = fmaf(xv.z, w2.z, acc[n][2]);
            acc[n][3] = fmaf(xv.z, w2.w, acc[n][3]);
            acc[n][0] = fmaf(xv.w, w3.x, acc[n][0]);
            acc[n][1] = fmaf(xv.w, w3.y, acc[n][1]);
            acc[n][2] = fmaf(xv.w, w3.z, acc[n][2]);
            acc[n][3] = fmaf(xv.w, w3.w, acc[n][3]);
        }
    }

    // per-head attention logits; lane covers cols lane*4..lane*4+3 (one head)
    const int head = lane >> 3;
    const int cb   = (lane & 7) * 4;
    float4 av = *(const float4*)&att_s[head * CC + cb];
    float4 bv = *(const float4*)&att_d[head * CC + cb];
#pragma unroll
    for (int n = 0; n < 4; n++) {
        const int node = nb + warp * 4 + n;
        // fp16 store of h row (logits below use full fp32 acc)
        __half2 h0 = __floats2half2_rn(acc[n][0], acc[n][1]);
        __half2 h1 = __floats2half2_rn(acc[n][2], acc[n][3]);
        uint2 pk;
        pk.x = *(unsigned*)&h0;
        pk.y = *(unsigned*)&h1;
        *(uint2*)&g_h2[(size_t)node * (DIM / 2) + lane * 2] = pk;

        float ps = acc[n][0]*av.x + acc[n][1]*av.y + acc[n][2]*av.z + acc[n][3]*av.w;
        float pd = acc[n][0]*bv.x + acc[n][1]*bv.y + acc[n][2]*bv.z + acc[n][3]*bv.w;
#pragma unroll
        for (int off = 4; off; off >>= 1) {
            ps += __shfl_down_sync(0xffffffffu, ps, off, 8);
            pd += __shfl_down_sync(0xffffffffu, pd, off, 8);
        }
        if ((lane & 7) == 0) {
            g_asrc[node * HH + head] = ps;
            g_adst[node * HH + head] = pd;
        }
    }
}

// ---------------- 2. weighted scatter-add, 4 edges per warp ----------------
// Softmax without max-shift: logits bounded (|l| <~ 6), exp(l)/sum(exp(l))
// is exact in fp32. edge_index int32 [2,E]; self-loops appended virtually.
__global__ void passB_kernel(const int* __restrict__ ei) {
    const int wid  = (blockIdx.x * blockDim.x + threadIdx.x) >> 5;  // warp id
    const int lane = threadIdx.x & 31;
    const int base = wid * 4;                 // first of 4 edges (< ETOT)

    // lanes 0-3 load src[e], lanes 4-7 load dst[e]; self-loop for id >= EE
    int v = 0;
    if (lane < 8) {
        int id = base + (lane & 3);
        if (lane < 4) v = (id < EE) ? __ldg(&ei[id])      : id - EE;
        else          v = (id < EE) ? __ldg(&ei[EE + id]) : id - EE;
    }
    int src[4], dst[4];
#pragma unroll
    for (int e = 0; e < 4; e++) {
        src[e] = __shfl_sync(0xffffffffu, v, e);
        dst[e] = __shfl_sync(0xffffffffu, v, 4 + e);
    }

    // lanes 0-15 own (e = lane>>2, h = lane&3); 16-31 duplicate harmlessly
    const int pe = (lane >> 2) & 3, ph = lane & 3;
    float l = __ldg(&g_asrc[src[pe] * HH + ph]) + __ldg(&g_adst[dst[pe] * HH + ph]);
    l = l > 0.f ? l : NEG_SLOPE * l;
    float p = __expf(l);
    if (lane < 16) atomicAdd(&g_s[dst[pe] * HH + ph], p);

    // 4 independent fp16 row gathers issued back-to-back (MLP = 4, 256B rows)
    uint2 raw[4];
#pragma unroll
    for (int e = 0; e < 4; e++)
        raw[e] = *(const uint2*)&g_h2[(size_t)src[e] * (DIM / 2) + lane * 2];

    const int myh = lane >> 3;                // head for this lane's columns
#pragma unroll
    for (int e = 0; e < 4; e++) {
        float pw = __shfl_sync(0xffffffffu, p, e * 4 + myh);
        float2 f0 = __half22float2(*(__half2*)&raw[e].x);
        float2 f1 = __half22float2(*(__half2*)&raw[e].y);
        float* dp = &g_acc[(size_t)dst[e] * DIM + lane * 4];
        asm volatile("red.global.add.v4.f32 [%0], {%1, %2, %3, %4};"
                     :: "l"(dp), "f"(f0.x * pw), "f"(f0.y * pw),
                        "f"(f1.x * pw), "f"(f1.y * pw)
                     : "memory");
    }
}

// ---------------- 3. BN column stats (read-only; no write-back) ------------
// one warp per group of 8 nodes; lane -> channel quad. Block-reduce in smem.
#define PC_WARPS 8
#define PC_NODES 8
__global__ void passC_kernel(const float* __restrict__ bias) {
    __shared__ float4 s_sum[PC_WARPS * 32];
    __shared__ float4 s_sq [PC_WARPS * 32];
    const int warp = threadIdx.x >> 5, lane = threadIdx.x & 31;
    const int head = lane >> 3;
    const float4 bv = *(const float4*)&bias[lane * 4];

    float4 sum = make_float4(0.f, 0.f, 0.f, 0.f);
    float4 sq  = make_float4(0.f, 0.f, 0.f, 0.f);
    const int node0 = (blockIdx.x * PC_WARPS + warp) * PC_NODES;
#pragma unroll
    for (int i = 0; i < PC_NODES; i++) {
        int node = node0 + i;
        if (node >= NN) break;
        float r = 1.f / (__ldg(&g_s[node * HH + head]) + 1e-16f);
        float4 a = *(const float4*)&g_acc[(size_t)node * DIM + lane * 4];
        float vx = fmaf(a.x, r, bv.x), vy = fmaf(a.y, r, bv.y);
        float vz = fmaf(a.z, r, bv.z), vw = fmaf(a.w, r, bv.w);
        sum.x += vx; sum.y += vy; sum.z += vz; sum.w += vw;
        sq.x = fmaf(vx, vx, sq.x); sq.y = fmaf(vy, vy, sq.y);
        sq.z = fmaf(vz, vz, sq.z); sq.w = fmaf(vw, vw, sq.w);
    }
    s_sum[warp * 32 + lane] = sum;
    s_sq [warp * 32 + lane] = sq;
    __syncthreads();
    if (warp == 0) {
#pragma unroll
        for (int w = 1; w < PC_WARPS; w++) {
            float4 a = s_sum[w * 32 + lane], b = s_sq[w * 32 + lane];
            sum.x += a.x; sum.y += a.y; sum.z += a.z; sum.w += a.w;
            sq.x  += b.x; sq.y  += b.y; sq.z  += b.z; sq.w  += b.w;
        }
        atomicAdd(&g_colsum[lane * 4 + 0], sum.x);
        atomicAdd(&g_colsum[lane * 4 + 1], sum.y);
        atomicAdd(&g_colsum[lane * 4 + 2], sum.z);
        atomicAdd(&g_colsum[lane * 4 + 3], sum.w);
        atomicAdd(&g_colsq[lane * 4 + 0], sq.x);
        atomicAdd(&g_colsq[lane * 4 + 1], sq.y);
        atomicAdd(&g_colsq[lane * 4 + 2], sq.z);
        atomicAdd(&g_colsq[lane * 4 + 3], sq.w);
    }
}

// ---------------- 4. fold BN stats into scale/shift -------------------------
__global__ void bn_kernel(const float* __restrict__ gamma,
                          const float* __restrict__ beta) {
    int c = threadIdx.x;
    float mean = g_colsum[c] * (1.f / NN);
    float var  = g_colsq[c] * (1.f / NN) - mean * mean;
    float sc   = gamma[c] * rsqrtf(var + BN_EPS);
    g_scale[c] = sc;
    g_shift[c] = beta[c] - mean * sc;
}

// ---------------- 5. normalize + bias + BN + residual + ReLU ---------------
__global__ void final_kernel(const float* __restrict__ x,
                             const float* __restrict__ bias,
                             float* __restrict__ out) {
    int i = blockIdx.x * blockDim.x + threadIdx.x;   // float4 index
    if (i >= NN * DIM / 4) return;
    int node = i >> 5, cq = i & 31, cb = cq * 4, head = cq >> 3;
    float r = 1.f / (__ldg(&g_s[node * HH + head]) + 1e-16f);
    float4 a  = ((const float4*)g_acc)[i];
    float4 xv = ((const float4*)x)[i];
    float4 bv = *(const float4*)&bias[cb];
    float4 sc = *(const float4*)&g_scale[cb];
    float4 sh = *(const float4*)&g_shift[cb];
    float4 o;
    o.x = fmaxf(fmaf(sc.x, fmaf(a.x, r, bv.x), sh.x) + xv.x, 0.f);
    o.y = fmaxf(fmaf(sc.y, fmaf(a.y, r, bv.y), sh.y) + xv.y, 0.f);
    o.z = fmaxf(fmaf(sc.z, fmaf(a.z, r, bv.z), sh.z) + xv.z, 0.f);
    o.w = fmaxf(fmaf(sc.w, fmaf(a.w, r, bv.w), sh.w) + xv.w, 0.f);
    ((float4*)out)[i] = o;
}

// ---------------- launch ----------------------------------------------------
extern "C" void kernel_launch(void* const* d_in, const int* in_sizes, int n_in,
                              void* d_out, int out_size) {
    const float* x     = (const float*)d_in[0];
    const int*   ei    = (const int*)d_in[1];      // int32 [2, E]
    const float* W     = (const float*)d_in[2];
    const float* att_s = (const float*)d_in[3];
    const float* att_d = (const float*)d_in[4];
    const float* bias  = (const float*)d_in[5];
    const float* gamma = (const float*)d_in[6];
    const float* beta  = (const float*)d_in[7];
    float*       out   = (float*)d_out;

    const int gemm_smem = (DIM * DIM + 32 * DIM) * sizeof(float);  // 80 KB
    cudaFuncSetAttribute(gemm_kernel, cudaFuncAttributeMaxDynamicSharedMemorySize,
                         gemm_smem);

    zero_kernel<<<(NN * HH + 255) / 256, 256>>>();
    gemm_kernel<<<NN / 32, 256, gemm_smem>>>(x, W, att_s, att_d);
    // 4 edges per warp, 8 warps per block: ETOT/4/8 = 53125 blocks exactly
    passB_kernel<<<ETOT / 4 / 8, 256>>>(ei);
    passC_kernel<<<(NN + PC_WARPS * PC_NODES - 1) / (PC_WARPS * PC_NODES), 256>>>(bias);
    bn_kernel<<<1, 128>>>(gamma, beta);
    final_kernel<<<(NN * 32 + 255) / 256, 256>>>(x, bias, out);
}

// round 7
// speedup vs baseline: 1.0581x; 1.0038x over previous
#include <cuda_runtime.h>
#include <cuda_fp16.h>

#define NN 100000
#define EE 1600000
#define HH 4
#define CC 32
#define DIM 128
#define NEG_SLOPE 0.2f
#define BN_EPS 1e-5f
#define NSCAN ((NN + 255) / 256)     // 391 scan blocks

// ---------------- scratch (static device globals; no allocs allowed) -------
__device__ __half2 g_h2[(size_t)NN * (DIM / 2)];  // x @ W in fp16 (25.6 MB)
__device__ float   g_acc[(size_t)NN * DIM];       // normalized+biased v (51.2 MB)
__device__ float   g_asrc[NN * HH];
__device__ float   g_adst[NN * HH];
__device__ int     g_deg[NN];
__device__ int     g_off[NN];
__device__ int     g_cur[NN];
__device__ int     g_bsum[NSCAN];
__device__ int     g_srcs[EE];                    // CSR src ids (6.4 MB)
__device__ float   g_colsum[DIM];
__device__ float   g_colsq[DIM];
__device__ float   g_scale[DIM];
__device__ float   g_shift[DIM];

// ---------------- 0. zero small scratch ------------------------------------
__global__ void zero_kernel() {
    int i = blockIdx.x * blockDim.x + threadIdx.x;
    if (i < NN) g_deg[i] = 0;
    if (i < DIM) { g_colsum[i] = 0.f; g_colsq[i] = 0.f; }
}

// ---------------- CSR build: histogram, scan, scatter -----------------------
__global__ void hist_kernel(const int* __restrict__ ei) {
    int e = blockIdx.x * blockDim.x + threadIdx.x;
    if (e < EE) atomicAdd(&g_deg[__ldg(&ei[EE + e])], 1);
}

__global__ void scan1_kernel() {                 // 256 elems per block
    __shared__ int ws[8];
    int tid = threadIdx.x;
    int i = blockIdx.x * 256 + tid;
    int v = (i < NN) ? g_deg[i] : 0;
    int x = v;
#pragma unroll
    for (int d = 1; d < 32; d <<= 1) {
        int y = __shfl_up_sync(0xffffffffu, x, d);
        if ((tid & 31) >= d) x += y;
    }
    if ((tid & 31) == 31) ws[tid >> 5] = x;
    __syncthreads();
    if (tid < 8) {
        int y = ws[tid], z = y;
#pragma unroll
        for (int d = 1; d < 8; d <<= 1) {
            int t = __shfl_up_sync(0xffu, z, d);
            if (tid >= d) z += t;
        }
        ws[tid] = z - y;                          // exclusive warp offsets
    }
    __syncthreads();
    int excl = x - v + ws[tid >> 5];
    if (i < NN) g_off[i] = excl;
    if (tid == 255) g_bsum[blockIdx.x] = excl + v;
}

__global__ void scan2_kernel() {                 // tiny serial scan of block sums
    if (threadIdx.x == 0) {
        int run = 0;
        for (int b = 0; b < NSCAN; b++) { int t = g_bsum[b]; g_bsum[b] = run; run += t; }
    }
}

__global__ void scan3_kernel() {
    int i = blockIdx.x * blockDim.x + threadIdx.x;
    if (i < NN) {
        int o = g_off[i] + g_bsum[i >> 8];
        g_off[i] = o;
        g_cur[i] = o;
    }
}

__global__ void scatter_kernel(const int* __restrict__ ei) {
    int e = blockIdx.x * blockDim.x + threadIdx.x;
    if (e < EE) {
        int s = __ldg(&ei[e]);
        int d = __ldg(&ei[EE + e]);
        int idx = atomicAdd(&g_cur[d], 1);
        g_srcs[idx] = s;
    }
}

// ---------------- 1. h = x @ W (fp32 math, fp16 store), attention logits ---
__global__ void gemm_kernel(const float* __restrict__ x,
                            const float* __restrict__ W,
                            const float* __restrict__ att_s,
                            const float* __restrict__ att_d) {
    extern __shared__ float sm[];
    float* ws = sm;                 // 128*128 = 64 KB
    float* xs = sm + DIM * DIM;     // 32*128  = 16 KB
    const int tid = threadIdx.x;
    const int nb  = blockIdx.x * 32;

    for (int i = tid * 4; i < DIM * DIM; i += 256 * 4)
        *(float4*)&ws[i] = *(const float4*)&W[i];
    for (int i = tid * 4; i < 32 * DIM; i += 256 * 4)
        *(float4*)&xs[i] = *(const float4*)&x[(size_t)nb * DIM + i];
    __syncthreads();

    const int warp = tid >> 5, lane = tid & 31;
    float acc[4][4];
#pragma unroll
    for (int n = 0; n < 4; n++)
#pragma unroll
        for (int j = 0; j < 4; j++) acc[n][j] = 0.f;

    const float* xrow = &xs[(warp * 4) * DIM];
#pragma unroll 8
    for (int k = 0; k < DIM; k += 4) {
        float4 w0 = *(float4*)&ws[(k + 0) * DIM + lane * 4];
        float4 w1 = *(float4*)&ws[(k + 1) * DIM + lane * 4];
        float4 w2 = *(float4*)&ws[(k + 2) * DIM + lane * 4];
        float4 w3 = *(float4*)&ws[(k + 3) * DIM + lane * 4];
#pragma unroll
        for (int n = 0; n < 4; n++) {
            float4 xv = *(float4*)&xrow[n * DIM + k];
            acc[n][0] = fmaf(xv.x, w0.x, acc[n][0]);
            acc[n][1] = fmaf(xv.x, w0.y, acc[n][1]);
            acc[n][2] = fmaf(xv.x, w0.z, acc[n][2]);
            acc[n][3] = fmaf(xv.x, w0.w, acc[n][3]);
            acc[n][0] = fmaf(xv.y, w1.x, acc[n][0]);
            acc[n][1] = fmaf(xv.y, w1.y, acc[n][1]);
            acc[n][2] = fmaf(xv.y, w1.z, acc[n][2]);
            acc[n][3] = fmaf(xv.y, w1.w, acc[n][3]);
            acc[n][0] = fmaf(xv.z, w2.x, acc[n][0]);
            acc[n][1] = fmaf(xv.z, w2.y, acc[n][1]);
            acc[n][2] = fmaf(xv.z, w2.z, acc[n][2]);
            acc[n][3] = fmaf(xv.z, w2.w, acc[n][3]);
            acc[n][0] = fmaf(xv.w, w3.x, acc[n][0]);
            acc[n][1] = fmaf(xv.w, w3.y, acc[n][1]);
            acc[n][2] = fmaf(xv.w, w3.z, acc[n][2]);
            acc[n][3] = fmaf(xv.w, w3.w, acc[n][3]);
        }
    }

    const int head = lane >> 3;
    const int cb   = (lane & 7) * 4;
    float4 av = *(const float4*)&att_s[head * CC + cb];
    float4 bv = *(const float4*)&att_d[head * CC + cb];
#pragma unroll
    for (int n = 0; n < 4; n++) {
        const int node = nb + warp * 4 + n;
        __half2 h0 = __floats2half2_rn(acc[n][0], acc[n][1]);
        __half2 h1 = __floats2half2_rn(acc[n][2], acc[n][3]);
        uint2 pk;
        pk.x = *(unsigned*)&h0;
        pk.y = *(unsigned*)&h1;
        *(uint2*)&g_h2[(size_t)node * (DIM / 2) + lane * 2] = pk;

        float ps = acc[n][0]*av.x + acc[n][1]*av.y + acc[n][2]*av.z + acc[n][3]*av.w;
        float pd = acc[n][0]*bv.x + acc[n][1]*bv.y + acc[n][2]*bv.z + acc[n][3]*bv.w;
#pragma unroll
        for (int off = 4; off; off >>= 1) {
            ps += __shfl_down_sync(0xffffffffu, ps, off, 8);
            pd += __shfl_down_sync(0xffffffffu, pd, off, 8);
        }
        if ((lane & 7) == 0) {
            g_asrc[node * HH + head] = ps;
            g_adst[node * HH + head] = pd;
        }
    }
}

// ---------------- 2. gather-aggregate, one warp per dst (no atomics) -------
// Softmax without max-shift (logits bounded). Writes v = agg/s + bias to
// g_acc once per row, and fuses BN column-stat accumulation.
#define AG_WARPS 8
#define AG_GRID  592
__global__ void agg_kernel(const float* __restrict__ bias) {
    __shared__ float4 s_sum[AG_WARPS * 32];
    __shared__ float4 s_sq [AG_WARPS * 32];
    const int warp = threadIdx.x >> 5, lane = threadIdx.x & 31;
    const int ph = lane & 3;           // head this lane's logit belongs to
    const int myh = lane >> 3;         // head of this lane's 4 columns
    const float4 bv = *(const float4*)&bias[lane * 4];

    float4 csum = make_float4(0.f, 0.f, 0.f, 0.f);
    float4 csq  = make_float4(0.f, 0.f, 0.f, 0.f);

    for (int dst = blockIdx.x * AG_WARPS + warp; dst < NN;
         dst += AG_GRID * AG_WARPS) {
        const float adst_ph = __ldg(&g_adst[dst * HH + ph]);

        // self loop
        float l0 = __ldg(&g_asrc[dst * HH + ph]) + adst_ph;
        l0 = l0 > 0.f ? l0 : NEG_SLOPE * l0;
        float p_self = __expf(l0);
        float s_part = (lane < 4) ? p_self : 0.f;   // one lane per head counts

        uint2 rself = *(const uint2*)&g_h2[(size_t)dst * (DIM / 2) + lane * 2];
        float pw0 = __shfl_sync(0xffffffffu, p_self, myh);
        float2 a0 = __half22float2(*(__half2*)&rself.x);
        float2 a1 = __half22float2(*(__half2*)&rself.y);
        float4 acc = make_float4(a0.x * pw0, a0.y * pw0, a1.x * pw0, a1.y * pw0);

        const int deg = g_deg[dst];
        const int off = g_off[dst];
        for (int b = 0; b < deg; b += 8) {
            const int nv = min(8, deg - b);
            int sv = 0;
            if (lane < nv) sv = __ldg(&g_srcs[off + b + lane]);
            int srcs[8];
#pragma unroll
            for (int e = 0; e < 8; e++)
                srcs[e] = __shfl_sync(0xffffffffu, sv, e);

            const int pe = lane >> 2;                 // edge this lane scores
            float p = 0.f;
            if (pe < nv) {
                float ll = __ldg(&g_asrc[srcs[pe] * HH + ph]) + adst_ph;
                ll = ll > 0.f ? ll : NEG_SLOPE * ll;
                p = __expf(ll);
            }
            s_part += p;

            uint2 raw[8];
#pragma unroll
            for (int e = 0; e < 8; e++)
                if (e < nv)                           // warp-uniform
                    raw[e] = *(const uint2*)&g_h2[(size_t)srcs[e] * (DIM / 2) + lane * 2];
#pragma unroll
            for (int e = 0; e < 8; e++) {
                if (e < nv) {
                    float pw = __shfl_sync(0xffffffffu, p, e * 4 + myh);
                    float2 f0 = __half22float2(*(__half2*)&raw[e].x);
                    float2 f1 = __half22float2(*(__half2*)&raw[e].y);
                    acc.x = fmaf(f0.x, pw, acc.x);
                    acc.y = fmaf(f0.y, pw, acc.y);
                    acc.z = fmaf(f1.x, pw, acc.z);
                    acc.w = fmaf(f1.y, pw, acc.w);
                }
            }
        }

        // total exp-sum per head: reduce over lanes sharing ph
        float st = s_part;
        st += __shfl_xor_sync(0xffffffffu, st, 4);
        st += __shfl_xor_sync(0xffffffffu, st, 8);
        st += __shfl_xor_sync(0xffffffffu, st, 16);
        float r = 1.f / (__shfl_sync(0xffffffffu, st, myh) + 1e-16f);

        float4 v;
        v.x = fmaf(acc.x, r, bv.x);
        v.y = fmaf(acc.y, r, bv.y);
        v.z = fmaf(acc.z, r, bv.z);
        v.w = fmaf(acc.w, r, bv.w);
        *(float4*)&g_acc[(size_t)dst * DIM + lane * 4] = v;

        csum.x += v.x; csum.y += v.y; csum.z += v.z; csum.w += v.w;
        csq.x = fmaf(v.x, v.x, csq.x); csq.y = fmaf(v.y, v.y, csq.y);
        csq.z = fmaf(v.z, v.z, csq.z); csq.w = fmaf(v.w, v.w, csq.w);
    }

    s_sum[warp * 32 + lane] = csum;
    s_sq [warp * 32 + lane] = csq;
    __syncthreads();
    if (warp == 0) {
#pragma unroll
        for (int w = 1; w < AG_WARPS; w++) {
            float4 a = s_sum[w * 32 + lane], b = s_sq[w * 32 + lane];
            csum.x += a.x; csum.y += a.y; csum.z += a.z; csum.w += a.w;
            csq.x  += b.x; csq.y  += b.y; csq.z  += b.z; csq.w  += b.w;
        }
        atomicAdd(&g_colsum[lane * 4 + 0], csum.x);
        atomicAdd(&g_colsum[lane * 4 + 1], csum.y);
        atomicAdd(&g_colsum[lane * 4 + 2], csum.z);
        atomicAdd(&g_colsum[lane * 4 + 3], csum.w);
        atomicAdd(&g_colsq[lane * 4 + 0], csq.x);
        atomicAdd(&g_colsq[lane * 4 + 1], csq.y);
        atomicAdd(&g_colsq[lane * 4 + 2], csq.z);
        atomicAdd(&g_colsq[lane * 4 + 3], csq.w);
    }
}

// ---------------- 3. fold BN stats into scale/shift -------------------------
__global__ void bn_kernel(const float* __restrict__ gamma,
                          const float* __restrict__ beta) {
    int c = threadIdx.x;
    float mean = g_colsum[c] * (1.f / NN);
    float var  = g_colsq[c] * (1.f / NN) - mean * mean;
    float sc   = gamma[c] * rsqrtf(var + BN_EPS);
    g_scale[c] = sc;
    g_shift[c] = beta[c] - mean * sc;
}

// ---------------- 4. BN apply + residual + ReLU ----------------------------
__global__ void final_kernel(const float* __restrict__ x,
                             float* __restrict__ out) {
    int i = blockIdx.x * blockDim.x + threadIdx.x;   // float4 index
    if (i >= NN * DIM / 4) return;
    int cb = (i & 31) * 4;
    float4 v  = ((const float4*)g_acc)[i];
    float4 xv = ((const float4*)x)[i];
    float4 sc = *(const float4*)&g_scale[cb];
    float4 sh = *(const float4*)&g_shift[cb];
    float4 o;
    o.x = fmaxf(fmaf(sc.x, v.x, sh.x) + xv.x, 0.f);
    o.y = fmaxf(fmaf(sc.y, v.y, sh.y) + xv.y, 0.f);
    o.z = fmaxf(fmaf(sc.z, v.z, sh.z) + xv.z, 0.f);
    o.w = fmaxf(fmaf(sc.w, v.w, sh.w) + xv.w, 0.f);
    ((float4*)out)[i] = o;
}

// ---------------- launch ----------------------------------------------------
extern "C" void kernel_launch(void* const* d_in, const int* in_sizes, int n_in,
                              void* d_out, int out_size) {
    const float* x     = (const float*)d_in[0];
    const int*   ei    = (const int*)d_in[1];      // int32 [2, E]
    const float* W     = (const float*)d_in[2];
    const float* att_s = (const float*)d_in[3];
    const float* att_d = (const float*)d_in[4];
    const float* bias  = (const float*)d_in[5];
    const float* gamma = (const float*)d_in[6];
    const float* beta  = (const float*)d_in[7];
    float*       out   = (float*)d_out;

    const int gemm_smem = (DIM * DIM + 32 * DIM) * sizeof(float);  // 80 KB
    cudaFuncSetAttribute(gemm_kernel, cudaFuncAttributeMaxDynamicSharedMemorySize,
                         gemm_smem);

    zero_kernel<<<(NN + 255) / 256, 256>>>();
    hist_kernel<<<(EE + 255) / 256, 256>>>(ei);
    scan1_kernel<<<NSCAN, 256>>>();
    scan2_kernel<<<1, 32>>>();
    scan3_kernel<<<(NN + 255) / 256, 256>>>();
    scatter_kernel<<<(EE + 255) / 256, 256>>>(ei);
    gemm_kernel<<<NN / 32, 256, gemm_smem>>>(x, W, att_s, att_d);
    agg_kernel<<<AG_GRID, AG_WARPS * 32>>>(bias);
    bn_kernel<<<1, 128>>>(gamma, beta);
    final_kernel<<<(NN * 32 + 255) / 256, 256>>>(x, out);
}

// round 8
// speedup vs baseline: 1.1276x; 1.0657x over previous
#include <cuda_runtime.h>
#include <cuda_fp16.h>

#define NN 100000
#define EE 1600000
#define HH 4
#define CC 32
#define DIM 128
#define NEG_SLOPE 0.2f
#define BN_EPS 1e-5f
#define NSCAN ((NN + 255) / 256)     // 391 scan blocks

// ---------------- scratch (static device globals; no allocs allowed) -------
__device__ __half2 g_h2[(size_t)NN * (DIM / 2)];  // x @ W in fp16 (25.6 MB)
__device__ float   g_acc[(size_t)NN * DIM];       // normalized+biased v (51.2 MB)
__device__ float   g_asrc[NN * HH];
__device__ float   g_adst[NN * HH];
__device__ int     g_deg[NN];
__device__ int     g_off[NN];
__device__ int     g_cur[NN];
__device__ int     g_bsum[NSCAN];
__device__ int     g_srcs[EE];                    // CSR src ids (6.4 MB)
__device__ float   g_colsum[DIM];
__device__ float   g_colsq[DIM];
__device__ float   g_scale[DIM];
__device__ float   g_shift[DIM];

// ---------------- 0. zero small scratch ------------------------------------
__global__ void zero_kernel() {
    int i = blockIdx.x * blockDim.x + threadIdx.x;
    if (i < NN) g_deg[i] = 0;
    if (i < DIM) { g_colsum[i] = 0.f; g_colsq[i] = 0.f; }
}

// ---------------- CSR build: histogram, scan, scatter -----------------------
__global__ void hist_kernel(const int* __restrict__ ei) {
    int e = blockIdx.x * blockDim.x + threadIdx.x;
    if (e < EE) atomicAdd(&g_deg[__ldg(&ei[EE + e])], 1);
}

__global__ void scan1_kernel() {                 // 256 elems per block
    __shared__ int ws[8];
    int tid = threadIdx.x;
    int i = blockIdx.x * 256 + tid;
    int v = (i < NN) ? g_deg[i] : 0;
    int x = v;
#pragma unroll
    for (int d = 1; d < 32; d <<= 1) {
        int y = __shfl_up_sync(0xffffffffu, x, d);
        if ((tid & 31) >= d) x += y;
    }
    if ((tid & 31) == 31) ws[tid >> 5] = x;
    __syncthreads();
    if (tid < 8) {
        int y = ws[tid], z = y;
#pragma unroll
        for (int d = 1; d < 8; d <<= 1) {
            int t = __shfl_up_sync(0xffu, z, d);
            if (tid >= d) z += t;
        }
        ws[tid] = z - y;                          // exclusive warp offsets
    }
    __syncthreads();
    int excl = x - v + ws[tid >> 5];
    if (i < NN) g_off[i] = excl;
    if (tid == 255) g_bsum[blockIdx.x] = excl + v;
}

// parallel scan of the NSCAN block sums: one block, 512 threads
__global__ void scan2_kernel() {
    __shared__ int sm[512];
    int tid = threadIdx.x;
    int v = (tid < NSCAN) ? g_bsum[tid] : 0;
    sm[tid] = v;
    __syncthreads();
#pragma unroll
    for (int d = 1; d < 512; d <<= 1) {
        int t = (tid >= d) ? sm[tid - d] : 0;
        __syncthreads();
        sm[tid] += t;
        __syncthreads();
    }
    if (tid < NSCAN) g_bsum[tid] = sm[tid] - v;   // exclusive
}

__global__ void scan3_kernel() {
    int i = blockIdx.x * blockDim.x + threadIdx.x;
    if (i < NN) {
        int o = g_off[i] + g_bsum[i >> 8];
        g_off[i] = o;
        g_cur[i] = o;
    }
}

__global__ void scatter_kernel(const int* __restrict__ ei) {
    int e = blockIdx.x * blockDim.x + threadIdx.x;
    if (e < EE) {
        int s = __ldg(&ei[e]);
        int d = __ldg(&ei[EE + e]);
        int idx = atomicAdd(&g_cur[d], 1);
        g_srcs[idx] = s;
    }
}

// ---------------- 1. h = x @ W (fp32 math, fp16 store), attention logits ---
__global__ void gemm_kernel(const float* __restrict__ x,
                            const float* __restrict__ W,
                            const float* __restrict__ att_s,
                            const float* __restrict__ att_d) {
    extern __shared__ float sm[];
    float* ws = sm;                 // 128*128 = 64 KB
    float* xs = sm + DIM * DIM;     // 32*128  = 16 KB
    const int tid = threadIdx.x;
    const int nb  = blockIdx.x * 32;

    for (int i = tid * 4; i < DIM * DIM; i += 256 * 4)
        *(float4*)&ws[i] = *(const float4*)&W[i];
    for (int i = tid * 4; i < 32 * DIM; i += 256 * 4)
        *(float4*)&xs[i] = *(const float4*)&x[(size_t)nb * DIM + i];
    __syncthreads();

    const int warp = tid >> 5, lane = tid & 31;
    float acc[4][4];
#pragma unroll
    for (int n = 0; n < 4; n++)
#pragma unroll
        for (int j = 0; j < 4; j++) acc[n][j] = 0.f;

    const float* xrow = &xs[(warp * 4) * DIM];
#pragma unroll 8
    for (int k = 0; k < DIM; k += 4) {
        float4 w0 = *(float4*)&ws[(k + 0) * DIM + lane * 4];
        float4 w1 = *(float4*)&ws[(k + 1) * DIM + lane * 4];
        float4 w2 = *(float4*)&ws[(k + 2) * DIM + lane * 4];
        float4 w3 = *(float4*)&ws[(k + 3) * DIM + lane * 4];
#pragma unroll
        for (int n = 0; n < 4; n++) {
            float4 xv = *(float4*)&xrow[n * DIM + k];
            acc[n][0] = fmaf(xv.x, w0.x, acc[n][0]);
            acc[n][1] = fmaf(xv.x, w0.y, acc[n][1]);
            acc[n][2] = fmaf(xv.x, w0.z, acc[n][2]);
            acc[n][3] = fmaf(xv.x, w0.w, acc[n][3]);
            acc[n][0] = fmaf(xv.y, w1.x, acc[n][0]);
            acc[n][1] = fmaf(xv.y, w1.y, acc[n][1]);
            acc[n][2] = fmaf(xv.y, w1.z, acc[n][2]);
            acc[n][3] = fmaf(xv.y, w1.w, acc[n][3]);
            acc[n][0] = fmaf(xv.z, w2.x, acc[n][0]);
            acc[n][1] = fmaf(xv.z, w2.y, acc[n][1]);
            acc[n][2] = fmaf(xv.z, w2.z, acc[n][2]);
            acc[n][3] = fmaf(xv.z, w2.w, acc[n][3]);
            acc[n][0] = fmaf(xv.w, w3.x, acc[n][0]);
            acc[n][1] = fmaf(xv.w, w3.y, acc[n][1]);
            acc[n][2] = fmaf(xv.w, w3.z, acc[n][2]);
            acc[n][3] = fmaf(xv.w, w3.w, acc[n][3]);
        }
    }

    const int head = lane >> 3;
    const int cb   = (lane & 7) * 4;
    float4 av = *(const float4*)&att_s[head * CC + cb];
    float4 bv = *(const float4*)&att_d[head * CC + cb];
#pragma unroll
    for (int n = 0; n < 4; n++) {
        const int node = nb + warp * 4 + n;
        __half2 h0 = __floats2half2_rn(acc[n][0], acc[n][1]);
        __half2 h1 = __floats2half2_rn(acc[n][2], acc[n][3]);
        uint2 pk;
        pk.x = *(unsigned*)&h0;
        pk.y = *(unsigned*)&h1;
        *(uint2*)&g_h2[(size_t)node * (DIM / 2) + lane * 2] = pk;

        float ps = acc[n][0]*av.x + acc[n][1]*av.y + acc[n][2]*av.z + acc[n][3]*av.w;
        float pd = acc[n][0]*bv.x + acc[n][1]*bv.y + acc[n][2]*bv.z + acc[n][3]*bv.w;
#pragma unroll
        for (int off = 4; off; off >>= 1) {
            ps += __shfl_down_sync(0xffffffffu, ps, off, 8);
            pd += __shfl_down_sync(0xffffffffu, pd, off, 8);
        }
        if ((lane & 7) == 0) {
            g_asrc[node * HH + head] = ps;
            g_adst[node * HH + head] = pd;
        }
    }
}

// ---------------- 2. gather-aggregate, one warp per dst (no atomics) -------
// Softmax without max-shift (logits bounded). Writes v = agg/s + bias to
// g_acc once per row, and fuses BN column-stat accumulation.
#define AG_WARPS 8
#define AG_GRID  592
__global__ void agg_kernel(const float* __restrict__ bias) {
    __shared__ float4 s_sum[AG_WARPS * 32];
    __shared__ float4 s_sq [AG_WARPS * 32];
    const int warp = threadIdx.x >> 5, lane = threadIdx.x & 31;
    const int ph = lane & 3;           // head this lane's logit belongs to
    const int myh = lane >> 3;         // head of this lane's 4 columns
    const float4 bv = *(const float4*)&bias[lane * 4];

    float4 csum = make_float4(0.f, 0.f, 0.f, 0.f);
    float4 csq  = make_float4(0.f, 0.f, 0.f, 0.f);

    for (int dst = blockIdx.x * AG_WARPS + warp; dst < NN;
         dst += AG_GRID * AG_WARPS) {
        const float adst_ph = __ldg(&g_adst[dst * HH + ph]);

        // self loop
        float l0 = __ldg(&g_asrc[dst * HH + ph]) + adst_ph;
        l0 = l0 > 0.f ? l0 : NEG_SLOPE * l0;
        float p_self = __expf(l0);
        float s_part = (lane < 4) ? p_self : 0.f;   // one lane per head counts

        uint2 rself = *(const uint2*)&g_h2[(size_t)dst * (DIM / 2) + lane * 2];
        float pw0 = __shfl_sync(0xffffffffu, p_self, myh);
        float2 a0 = __half22float2(*(__half2*)&rself.x);
        float2 a1 = __half22float2(*(__half2*)&rself.y);
        float4 acc = make_float4(a0.x * pw0, a0.y * pw0, a1.x * pw0, a1.y * pw0);

        const int deg = g_deg[dst];
        const int off = g_off[dst];
        for (int b = 0; b < deg; b += 8) {
            const int nv = min(8, deg - b);
            int sv = 0;
            if (lane < nv) sv = __ldg(&g_srcs[off + b + lane]);
            int srcs[8];
#pragma unroll
            for (int e = 0; e < 8; e++)
                srcs[e] = __shfl_sync(0xffffffffu, sv, e);

            const int pe = lane >> 2;                 // edge this lane scores
            float p = 0.f;
            if (pe < nv) {
                float ll = __ldg(&g_asrc[srcs[pe] * HH + ph]) + adst_ph;
                ll = ll > 0.f ? ll : NEG_SLOPE * ll;
                p = __expf(ll);
            }
            s_part += p;

            uint2 raw[8];
#pragma unroll
            for (int e = 0; e < 8; e++)
                if (e < nv)                           // warp-uniform
                    raw[e] = *(const uint2*)&g_h2[(size_t)srcs[e] * (DIM / 2) + lane * 2];
#pragma unroll
            for (int e = 0; e < 8; e++) {
                if (e < nv) {
                    float pw = __shfl_sync(0xffffffffu, p, e * 4 + myh);
                    float2 f0 = __half22float2(*(__half2*)&raw[e].x);
                    float2 f1 = __half22float2(*(__half2*)&raw[e].y);
                    acc.x = fmaf(f0.x, pw, acc.x);
                    acc.y = fmaf(f0.y, pw, acc.y);
                    acc.z = fmaf(f1.x, pw, acc.z);
                    acc.w = fmaf(f1.y, pw, acc.w);
                }
            }
        }

        // total exp-sum per head: reduce over lanes sharing ph
        float st = s_part;
        st += __shfl_xor_sync(0xffffffffu, st, 4);
        st += __shfl_xor_sync(0xffffffffu, st, 8);
        st += __shfl_xor_sync(0xffffffffu, st, 16);
        float r = 1.f / (__shfl_sync(0xffffffffu, st, myh) + 1e-16f);

        float4 v;
        v.x = fmaf(acc.x, r, bv.x);
        v.y = fmaf(acc.y, r, bv.y);
        v.z = fmaf(acc.z, r, bv.z);
        v.w = fmaf(acc.w, r, bv.w);
        *(float4*)&g_acc[(size_t)dst * DIM + lane * 4] = v;

        csum.x += v.x; csum.y += v.y; csum.z += v.z; csum.w += v.w;
        csq.x = fmaf(v.x, v.x, csq.x); csq.y = fmaf(v.y, v.y, csq.y);
        csq.z = fmaf(v.z, v.z, csq.z); csq.w = fmaf(v.w, v.w, csq.w);
    }

    s_sum[warp * 32 + lane] = csum;
    s_sq [warp * 32 + lane] = csq;
    __syncthreads();
    if (warp == 0) {
#pragma unroll
        for (int w = 1; w < AG_WARPS; w++) {
            float4 a = s_sum[w * 32 + lane], b = s_sq[w * 32 + lane];
            csum.x += a.x; csum.y += a.y; csum.z += a.z; csum.w += a.w;
            csq.x  += b.x; csq.y  += b.y; csq.z  += b.z; csq.w  += b.w;
        }
        atomicAdd(&g_colsum[lane * 4 + 0], csum.x);
        atomicAdd(&g_colsum[lane * 4 + 1], csum.y);
        atomicAdd(&g_colsum[lane * 4 + 2], csum.z);
        atomicAdd(&g_colsum[lane * 4 + 3], csum.w);
        atomicAdd(&g_colsq[lane * 4 + 0], csq.x);
        atomicAdd(&g_colsq[lane * 4 + 1], csq.y);
        atomicAdd(&g_colsq[lane * 4 + 2], csq.z);
        atomicAdd(&g_colsq[lane * 4 + 3], csq.w);
    }
}

// ---------------- 3. fold BN stats into scale/shift -------------------------
__global__ void bn_kernel(const float* __restrict__ gamma,
                          const float* __restrict__ beta) {
    int c = threadIdx.x;
    float mean = g_colsum[c] * (1.f / NN);
    float var  = g_colsq[c] * (1.f / NN) - mean * mean;
    float sc   = gamma[c] * rsqrtf(var + BN_EPS);
    g_scale[c] = sc;
    g_shift[c] = beta[c] - mean * sc;
}

// ---------------- 4. BN apply + residual + ReLU ----------------------------
__global__ void final_kernel(const float* __restrict__ x,
                             float* __restrict__ out) {
    int i = blockIdx.x * blockDim.x + threadIdx.x;   // float4 index
    if (i >= NN * DIM / 4) return;
    int cb = (i & 31) * 4;
    float4 v  = ((const float4*)g_acc)[i];
    float4 xv = ((const float4*)x)[i];
    float4 sc = *(const float4*)&g_scale[cb];
    float4 sh = *(const float4*)&g_shift[cb];
    float4 o;
    o.x = fmaxf(fmaf(sc.x, v.x, sh.x) + xv.x, 0.f);
    o.y = fmaxf(fmaf(sc.y, v.y, sh.y) + xv.y, 0.f);
    o.z = fmaxf(fmaf(sc.z, v.z, sh.z) + xv.z, 0.f);
    o.w = fmaxf(fmaf(sc.w, v.w, sh.w) + xv.w, 0.f);
    ((float4*)out)[i] = o;
}

// ---------------- launch ----------------------------------------------------
// CSR build (side stream) runs concurrently with gemm (main stream); they
// have no data dependence. Fork/join via events is graph-capture legal.
extern "C" void kernel_launch(void* const* d_in, const int* in_sizes, int n_in,
                              void* d_out, int out_size) {
    const float* x     = (const float*)d_in[0];
    const int*   ei    = (const int*)d_in[1];      // int32 [2, E]
    const float* W     = (const float*)d_in[2];
    const float* att_s = (const float*)d_in[3];
    const float* att_d = (const float*)d_in[4];
    const float* bias  = (const float*)d_in[5];
    const float* gamma = (const float*)d_in[6];
    const float* beta  = (const float*)d_in[7];
    float*       out   = (float*)d_out;

    const int gemm_smem = (DIM * DIM + 32 * DIM) * sizeof(float);  // 80 KB
    cudaFuncSetAttribute(gemm_kernel, cudaFuncAttributeMaxDynamicSharedMemorySize,
                         gemm_smem);

    cudaStream_t side;
    cudaStreamCreateWithFlags(&side, cudaStreamNonBlocking);
    cudaEvent_t eFork, eJoin;
    cudaEventCreateWithFlags(&eFork, cudaEventDisableTiming);
    cudaEventCreateWithFlags(&eJoin, cudaEventDisableTiming);

    // fork: side stream inherits capture dependency from main stream
    cudaEventRecord(eFork, 0);
    cudaStreamWaitEvent(side, eFork, 0);

    // CSR build chain on side stream
    zero_kernel<<<(NN + 255) / 256, 256, 0, side>>>();
    hist_kernel<<<(EE + 255) / 256, 256, 0, side>>>(ei);
    scan1_kernel<<<NSCAN, 256, 0, side>>>();
    scan2_kernel<<<1, 512, 0, side>>>();
    scan3_kernel<<<(NN + 255) / 256, 256, 0, side>>>();
    scatter_kernel<<<(EE + 255) / 256, 256, 0, side>>>(ei);
    cudaEventRecord(eJoin, side);

    // gemm on main stream, concurrent with CSR build
    gemm_kernel<<<NN / 32, 256, gemm_smem>>>(x, W, att_s, att_d);

    // join: agg needs both gemm and CSR
    cudaStreamWaitEvent(0, eJoin, 0);
    agg_kernel<<<AG_GRID, AG_WARPS * 32>>>(bias);
    bn_kernel<<<1, 128>>>(gamma, beta);
    final_kernel<<<(NN * 32 + 255) / 256, 256>>>(x, out);
    // note: stream/events intentionally not destroyed here — capture may still
    // be active on them; they are host-side objects (no device allocations).
}

// round 9
// speedup vs baseline: 1.1874x; 1.0530x over previous
#include <cuda_runtime.h>
#include <cuda_fp16.h>

#define NN 100000
#define EE 1600000
#define HH 4
#define CC 32
#define DIM 128
#define NEG_SLOPE 0.2f
#define BN_EPS 1e-5f
#define NSCAN ((NN + 255) / 256)     // 391 scan blocks

// ---------------- scratch (static device globals; no allocs allowed) -------
__device__ __half2 g_h2[(size_t)NN * (DIM / 2)];  // x @ W in fp16 (25.6 MB)
__device__ float   g_acc[(size_t)NN * DIM];       // normalized+biased v (51.2 MB)
__device__ float   g_asrc[NN * HH];
__device__ float   g_adst[NN * HH];
__device__ int     g_deg[NN];
__device__ int     g_off[NN];
__device__ int     g_cur[NN];
__device__ int     g_bsum[NSCAN];
__device__ int     g_srcs[EE];                    // CSR src ids (6.4 MB)
__device__ float   g_colsum[DIM];
__device__ float   g_colsq[DIM];
__device__ float   g_scale[DIM];
__device__ float   g_shift[DIM];

// ---------------- 0. zero small scratch ------------------------------------
__global__ void zero_kernel() {
    int i = blockIdx.x * blockDim.x + threadIdx.x;
    if (i < NN) g_deg[i] = 0;
    if (i < DIM) { g_colsum[i] = 0.f; g_colsq[i] = 0.f; }
}

// ---------------- CSR build: histogram, scan, scatter -----------------------
__global__ void hist_kernel(const int* __restrict__ ei) {
    int e = blockIdx.x * blockDim.x + threadIdx.x;
    if (e < EE) atomicAdd(&g_deg[__ldg(&ei[EE + e])], 1);
}

__global__ void scan1_kernel() {                 // 256 elems per block
    __shared__ int ws[8];
    int tid = threadIdx.x;
    int i = blockIdx.x * 256 + tid;
    int v = (i < NN) ? g_deg[i] : 0;
    int x = v;
#pragma unroll
    for (int d = 1; d < 32; d <<= 1) {
        int y = __shfl_up_sync(0xffffffffu, x, d);
        if ((tid & 31) >= d) x += y;
    }
    if ((tid & 31) == 31) ws[tid >> 5] = x;
    __syncthreads();
    if (tid < 8) {
        int y = ws[tid], z = y;
#pragma unroll
        for (int d = 1; d < 8; d <<= 1) {
            int t = __shfl_up_sync(0xffu, z, d);
            if (tid >= d) z += t;
        }
        ws[tid] = z - y;                          // exclusive warp offsets
    }
    __syncthreads();
    int excl = x - v + ws[tid >> 5];
    if (i < NN) g_off[i] = excl;
    if (tid == 255) g_bsum[blockIdx.x] = excl + v;
}

// parallel scan of the NSCAN block sums: one block, 512 threads
__global__ void scan2_kernel() {
    __shared__ int sm[512];
    int tid = threadIdx.x;
    int v = (tid < NSCAN) ? g_bsum[tid] : 0;
    sm[tid] = v;
    __syncthreads();
#pragma unroll
    for (int d = 1; d < 512; d <<= 1) {
        int t = (tid >= d) ? sm[tid - d] : 0;
        __syncthreads();
        sm[tid] += t;
        __syncthreads();
    }
    if (tid < NSCAN) g_bsum[tid] = sm[tid] - v;   // exclusive
}

__global__ void scan3_kernel() {
    int i = blockIdx.x * blockDim.x + threadIdx.x;
    if (i < NN) {
        int o = g_off[i] + g_bsum[i >> 8];
        g_off[i] = o;
        g_cur[i] = o;
    }
}

__global__ void scatter_kernel(const int* __restrict__ ei) {
    int e = blockIdx.x * blockDim.x + threadIdx.x;
    if (e < EE) {
        int s = __ldg(&ei[e]);
        int d = __ldg(&ei[EE + e]);
        int idx = atomicAdd(&g_cur[d], 1);
        g_srcs[idx] = s;
    }
}

// ---------------- 1. h = x @ W (fp32 math, fp16 store), attention logits ---
// 256 threads, 64 nodes per block (8 per warp), W fully staged in SMEM.
#define GN 64
__global__ void gemm_kernel(const float* __restrict__ x,
                            const float* __restrict__ W,
                            const float* __restrict__ att_s,
                            const float* __restrict__ att_d) {
    extern __shared__ float sm[];
    float* ws = sm;                 // 128*128 = 64 KB
    float* xs = sm + DIM * DIM;     // 64*128  = 32 KB
    const int tid = threadIdx.x;
    const int nb  = blockIdx.x * GN;

    for (int i = tid * 4; i < DIM * DIM; i += 256 * 4)
        *(float4*)&ws[i] = *(const float4*)&W[i];
    for (int i = tid * 4; i < GN * DIM; i += 256 * 4) {
        size_t g = (size_t)nb * DIM + i;
        if (g < (size_t)NN * DIM) *(float4*)&xs[i] = *(const float4*)&x[g];
        else *(float4*)&xs[i] = make_float4(0.f, 0.f, 0.f, 0.f);
    }
    __syncthreads();

    const int warp = tid >> 5, lane = tid & 31;
    float acc[8][4];
#pragma unroll
    for (int n = 0; n < 8; n++)
#pragma unroll
        for (int j = 0; j < 4; j++) acc[n][j] = 0.f;

    const float* xrow = &xs[(warp * 8) * DIM];
#pragma unroll 4
    for (int k = 0; k < DIM; k += 4) {
        float4 w0 = *(float4*)&ws[(k + 0) * DIM + lane * 4];
        float4 w1 = *(float4*)&ws[(k + 1) * DIM + lane * 4];
        float4 w2 = *(float4*)&ws[(k + 2) * DIM + lane * 4];
        float4 w3 = *(float4*)&ws[(k + 3) * DIM + lane * 4];
#pragma unroll
        for (int n = 0; n < 8; n++) {
            float4 xv = *(float4*)&xrow[n * DIM + k];
            acc[n][0] = fmaf(xv.x, w0.x, acc[n][0]);
            acc[n][1] = fmaf(xv.x, w0.y, acc[n][1]);
            acc[n][2] = fmaf(xv.x, w0.z, acc[n][2]);
            acc[n][3] = fmaf(xv.x, w0.w, acc[n][3]);
            acc[n][0] = fmaf(xv.y, w1.x, acc[n][0]);
            acc[n][1] = fmaf(xv.y, w1.y, acc[n][1]);
            acc[n][2] = fmaf(xv.y, w1.z, acc[n][2]);
            acc[n][3] = fmaf(xv.y, w1.w, acc[n][3]);
            acc[n][0] = fmaf(xv.z, w2.x, acc[n][0]);
            acc[n][1] = fmaf(xv.z, w2.y, acc[n][1]);
            acc[n][2] = fmaf(xv.z, w2.z, acc[n][2]);
            acc[n][3] = fmaf(xv.z, w2.w, acc[n][3]);
            acc[n][0] = fmaf(xv.w, w3.x, acc[n][0]);
            acc[n][1] = fmaf(xv.w, w3.y, acc[n][1]);
            acc[n][2] = fmaf(xv.w, w3.z, acc[n][2]);
            acc[n][3] = fmaf(xv.w, w3.w, acc[n][3]);
        }
    }

    const int head = lane >> 3;
    const int cb   = (lane & 7) * 4;
    float4 av = *(const float4*)&att_s[head * CC + cb];
    float4 bv = *(const float4*)&att_d[head * CC + cb];
#pragma unroll
    for (int n = 0; n < 8; n++) {
        const int node = nb + warp * 8 + n;
        if (node < NN) {                               // warp-uniform
            __half2 h0 = __floats2half2_rn(acc[n][0], acc[n][1]);
            __half2 h1 = __floats2half2_rn(acc[n][2], acc[n][3]);
            uint2 pk;
            pk.x = *(unsigned*)&h0;
            pk.y = *(unsigned*)&h1;
            *(uint2*)&g_h2[(size_t)node * (DIM / 2) + lane * 2] = pk;

            float ps = acc[n][0]*av.x + acc[n][1]*av.y + acc[n][2]*av.z + acc[n][3]*av.w;
            float pd = acc[n][0]*bv.x + acc[n][1]*bv.y + acc[n][2]*bv.z + acc[n][3]*bv.w;
#pragma unroll
            for (int off = 4; off; off >>= 1) {
                ps += __shfl_down_sync(0xffffffffu, ps, off, 8);
                pd += __shfl_down_sync(0xffffffffu, pd, off, 8);
            }
            if ((lane & 7) == 0) {
                g_asrc[node * HH + head] = ps;
                g_adst[node * HH + head] = pd;
            }
        }
    }
}

// ---------------- 2. gather-aggregate, one warp per dst (no atomics) -------
// Softmax without max-shift (logits bounded). Writes v = agg/s + bias to
// g_acc once per row, and fuses BN column-stat accumulation.
// 32 src ids loaded coalesced per chunk; 16 row gathers in flight; all
// register-array indices are compile-time (shfl used for lane-varying reads).
#define AG_WARPS 8
#define AG_GRID  592
__global__ void agg_kernel(const float* __restrict__ bias) {
    __shared__ float4 s_sum[AG_WARPS * 32];
    __shared__ float4 s_sq [AG_WARPS * 32];
    const int warp = threadIdx.x >> 5, lane = threadIdx.x & 31;
    const int ph = lane & 3;           // head this lane's logit belongs to
    const int pe = lane >> 2;          // edge slot (0..7) this lane scores
    const int myh = lane >> 3;         // head of this lane's 4 columns
    const float4 bv = *(const float4*)&bias[lane * 4];

    float4 csum = make_float4(0.f, 0.f, 0.f, 0.f);
    float4 csq  = make_float4(0.f, 0.f, 0.f, 0.f);

    for (int dst = blockIdx.x * AG_WARPS + warp; dst < NN;
         dst += AG_GRID * AG_WARPS) {
        const float adst_ph = __ldg(&g_adst[dst * HH + ph]);

        // self loop
        float l0 = __ldg(&g_asrc[dst * HH + ph]) + adst_ph;
        l0 = l0 > 0.f ? l0 : NEG_SLOPE * l0;
        float p_self = __expf(l0);
        float s_part = (lane < 4) ? p_self : 0.f;   // one lane per head counts

        uint2 rself = *(const uint2*)&g_h2[(size_t)dst * (DIM / 2) + lane * 2];
        float pw0 = __shfl_sync(0xffffffffu, p_self, myh);
        float2 a0 = __half22float2(*(__half2*)&rself.x);
        float2 a1 = __half22float2(*(__half2*)&rself.y);
        float4 acc = make_float4(a0.x * pw0, a0.y * pw0, a1.x * pw0, a1.y * pw0);

        const int deg = g_deg[dst];
        const int off = g_off[dst];
        for (int c = 0; c < deg; c += 32) {
            const int nc = min(32, deg - c);
            int sv = 0;
            if (lane < nc) sv = __ldg(&g_srcs[off + c + lane]);

#pragma unroll
            for (int h = 0; h < 2; h++) {
                const int e0 = h * 16;
                const int nv = nc - e0;               // valid edges this half
                if (nv <= 0) break;

                // logits: lane scores edges e0+pe and e0+pe+8 (head ph)
                float pA = 0.f, pB = 0.f;
                int sA = __shfl_sync(0xffffffffu, sv, e0 + pe);
                int sB = __shfl_sync(0xffffffffu, sv, e0 + pe + 8);
                if (pe < nv) {
                    float ll = __ldg(&g_asrc[sA * HH + ph]) + adst_ph;
                    ll = ll > 0.f ? ll : NEG_SLOPE * ll;
                    pA = __expf(ll);
                }
                if (pe + 8 < nv) {
                    float ll = __ldg(&g_asrc[sB * HH + ph]) + adst_ph;
                    ll = ll > 0.f ? ll : NEG_SLOPE * ll;
                    pB = __expf(ll);
                }
                s_part += pA + pB;

                // 16 independent row gathers (constant indices only)
                uint2 raw[16];
#pragma unroll
                for (int e = 0; e < 16; e++) {
                    if (e < nv) {                     // warp-uniform
                        int se = __shfl_sync(0xffffffffu, sv, e0 + e);
                        raw[e] = *(const uint2*)&g_h2[(size_t)se * (DIM / 2) + lane * 2];
                    }
                }
#pragma unroll
                for (int e = 0; e < 16; e++) {
                    if (e < nv) {
                        float pw = (e < 8)
                            ? __shfl_sync(0xffffffffu, pA, e * 4 + myh)
                            : __shfl_sync(0xffffffffu, pB, (e - 8) * 4 + myh);
                        float2 f0 = __half22float2(*(__half2*)&raw[e].x);
                        float2 f1 = __half22float2(*(__half2*)&raw[e].y);
                        acc.x = fmaf(f0.x, pw, acc.x);
                        acc.y = fmaf(f0.y, pw, acc.y);
                        acc.z = fmaf(f1.x, pw, acc.z);
                        acc.w = fmaf(f1.y, pw, acc.w);
                    }
                }
            }
        }

        // total exp-sum per head: reduce over lanes sharing ph
        float st = s_part;
        st += __shfl_xor_sync(0xffffffffu, st, 4);
        st += __shfl_xor_sync(0xffffffffu, st, 8);
        st += __shfl_xor_sync(0xffffffffu, st, 16);
        float r = 1.f / (__shfl_sync(0xffffffffu, st, myh) + 1e-16f);

        float4 v;
        v.x = fmaf(acc.x, r, bv.x);
        v.y = fmaf(acc.y, r, bv.y);
        v.z = fmaf(acc.z, r, bv.z);
        v.w = fmaf(acc.w, r, bv.w);
        *(float4*)&g_acc[(size_t)dst * DIM + lane * 4] = v;

        csum.x += v.x; csum.y += v.y; csum.z += v.z; csum.w += v.w;
        csq.x = fmaf(v.x, v.x, csq.x); csq.y = fmaf(v.y, v.y, csq.y);
        csq.z = fmaf(v.z, v.z, csq.z); csq.w = fmaf(v.w, v.w, csq.w);
    }

    s_sum[warp * 32 + lane] = csum;
    s_sq [warp * 32 + lane] = csq;
    __syncthreads();
    if (warp == 0) {
#pragma unroll
        for (int w = 1; w < AG_WARPS; w++) {
            float4 a = s_sum[w * 32 + lane], b = s_sq[w * 32 + lane];
            csum.x += a.x; csum.y += a.y; csum.z += a.z; csum.w += a.w;
            csq.x  += b.x; csq.y  += b.y; csq.z  += b.z; csq.w  += b.w;
        }
        atomicAdd(&g_colsum[lane * 4 + 0], csum.x);
        atomicAdd(&g_colsum[lane * 4 + 1], csum.y);
        atomicAdd(&g_colsum[lane * 4 + 2], csum.z);
        atomicAdd(&g_colsum[lane * 4 + 3], csum.w);
        atomicAdd(&g_colsq[lane * 4 + 0], csq.x);
        atomicAdd(&g_colsq[lane * 4 + 1], csq.y);
        atomicAdd(&g_colsq[lane * 4 + 2], csq.z);
        atomicAdd(&g_colsq[lane * 4 + 3], csq.w);
    }
}

// ---------------- 3. fold BN stats into scale/shift -------------------------
__global__ void bn_kernel(const float* __restrict__ gamma,
                          const float* __restrict__ beta) {
    int c = threadIdx.x;
    float mean = g_colsum[c] * (1.f / NN);
    float var  = g_colsq[c] * (1.f / NN) - mean * mean;
    float sc   = gamma[c] * rsqrtf(var + BN_EPS);
    g_scale[c] = sc;
    g_shift[c] = beta[c] - mean * sc;
}

// ---------------- 4. BN apply + residual + ReLU ----------------------------
__global__ void final_kernel(const float* __restrict__ x,
                             float* __restrict__ out) {
    int i = blockIdx.x * blockDim.x + threadIdx.x;   // float4 index
    if (i >= NN * DIM / 4) return;
    int cb = (i & 31) * 4;
    float4 v  = ((const float4*)g_acc)[i];
    float4 xv = ((const float4*)x)[i];
    float4 sc = *(const float4*)&g_scale[cb];
    float4 sh = *(const float4*)&g_shift[cb];
    float4 o;
    o.x = fmaxf(fmaf(sc.x, v.x, sh.x) + xv.x, 0.f);
    o.y = fmaxf(fmaf(sc.y, v.y, sh.y) + xv.y, 0.f);
    o.z = fmaxf(fmaf(sc.z, v.z, sh.z) + xv.z, 0.f);
    o.w = fmaxf(fmaf(sc.w, v.w, sh.w) + xv.w, 0.f);
    ((float4*)out)[i] = o;
}

// ---------------- launch ----------------------------------------------------
// CSR build (side stream) runs concurrently with gemm (main stream); they
// have no data dependence. Fork/join via events is graph-capture legal.
extern "C" void kernel_launch(void* const* d_in, const int* in_sizes, int n_in,
                              void* d_out, int out_size) {
    const float* x     = (const float*)d_in[0];
    const int*   ei    = (const int*)d_in[1];      // int32 [2, E]
    const float* W     = (const float*)d_in[2];
    const float* att_s = (const float*)d_in[3];
    const float* att_d = (const float*)d_in[4];
    const float* bias  = (const float*)d_in[5];
    const float* gamma = (const float*)d_in[6];
    const float* beta  = (const float*)d_in[7];
    float*       out   = (float*)d_out;

    const int gemm_smem = (DIM * DIM + GN * DIM) * sizeof(float);  // 96 KB
    cudaFuncSetAttribute(gemm_kernel, cudaFuncAttributeMaxDynamicSharedMemorySize,
                         gemm_smem);

    cudaStream_t side;
    cudaStreamCreateWithFlags(&side, cudaStreamNonBlocking);
    cudaEvent_t eFork, eJoin;
    cudaEventCreateWithFlags(&eFork, cudaEventDisableTiming);
    cudaEventCreateWithFlags(&eJoin, cudaEventDisableTiming);

    // fork: side stream inherits capture dependency from main stream
    cudaEventRecord(eFork, 0);
    cudaStreamWaitEvent(side, eFork, 0);

    // CSR build chain on side stream
    zero_kernel<<<(NN + 255) / 256, 256, 0, side>>>();
    hist_kernel<<<(EE + 255) / 256, 256, 0, side>>>(ei);
    scan1_kernel<<<NSCAN, 256, 0, side>>>();
    scan2_kernel<<<1, 512, 0, side>>>();
    scan3_kernel<<<(NN + 255) / 256, 256, 0, side>>>();
    scatter_kernel<<<(EE + 255) / 256, 256, 0, side>>>(ei);
    cudaEventRecord(eJoin, side);

    // gemm on main stream, concurrent with CSR build
    gemm_kernel<<<(NN + GN - 1) / GN, 256, gemm_smem>>>(x, W, att_s, att_d);

    // join: agg needs both gemm and CSR
    cudaStreamWaitEvent(0, eJoin, 0);
    agg_kernel<<<AG_GRID, AG_WARPS * 32>>>(bias);
    bn_kernel<<<1, 128>>>(gamma, beta);
    final_kernel<<<(NN * 32 + 255) / 256, 256>>>(x, out);
    // note: stream/events intentionally not destroyed here — capture may still
    // be active on them; they are host-side objects (no device allocations).
}

// round 10
// speedup vs baseline: 1.2431x; 1.0470x over previous
#include <cuda_runtime.h>
#include <cuda_fp16.h>

#define NN 100000
#define EE 1600000
#define HH 4
#define CC 32
#define DIM 128
#define NEG_SLOPE 0.2f
#define BN_EPS 1e-5f
#define NSCAN ((NN + 255) / 256)     // 391 scan blocks

// ---------------- scratch (static device globals; no allocs allowed) -------
__device__ __half2 g_h2[(size_t)NN * (DIM / 2)];  // x @ W in fp16 (25.6 MB)
__device__ float   g_acc[(size_t)NN * DIM];       // normalized+biased v (51.2 MB)
__device__ float   g_asrc[NN * HH];
__device__ float   g_adst[NN * HH];
__device__ int     g_deg[NN];
__device__ int     g_off[NN];
__device__ int     g_cur[NN];
__device__ int     g_bsum[NSCAN];
__device__ int     g_srcs[EE];                    // CSR src ids (6.4 MB)
__device__ float   g_colsum[DIM];
__device__ float   g_colsq[DIM];

// ---------------- 0. zero small scratch ------------------------------------
__global__ void zero_kernel() {
    int i = blockIdx.x * blockDim.x + threadIdx.x;
    if (i < NN) g_deg[i] = 0;
    if (i < DIM) { g_colsum[i] = 0.f; g_colsq[i] = 0.f; }
}

// ---------------- CSR build: histogram, scan, scatter -----------------------
__global__ void hist_kernel(const int* __restrict__ ei) {
    int e = blockIdx.x * blockDim.x + threadIdx.x;
    if (e < EE) atomicAdd(&g_deg[__ldg(&ei[EE + e])], 1);
}

__global__ void scan1_kernel() {                 // 256 elems per block
    __shared__ int ws[8];
    int tid = threadIdx.x;
    int i = blockIdx.x * 256 + tid;
    int v = (i < NN) ? g_deg[i] : 0;
    int x = v;
#pragma unroll
    for (int d = 1; d < 32; d <<= 1) {
        int y = __shfl_up_sync(0xffffffffu, x, d);
        if ((tid & 31) >= d) x += y;
    }
    if ((tid & 31) == 31) ws[tid >> 5] = x;
    __syncthreads();
    if (tid < 8) {
        int y = ws[tid], z = y;
#pragma unroll
        for (int d = 1; d < 8; d <<= 1) {
            int t = __shfl_up_sync(0xffu, z, d);
            if (tid >= d) z += t;
        }
        ws[tid] = z - y;                          // exclusive warp offsets
    }
    __syncthreads();
    int excl = x - v + ws[tid >> 5];
    if (i < NN) g_off[i] = excl;
    if (tid == 255) g_bsum[blockIdx.x] = excl + v;
}

// parallel scan of the NSCAN block sums: one block, 512 threads
__global__ void scan2_kernel() {
    __shared__ int sm[512];
    int tid = threadIdx.x;
    int v = (tid < NSCAN) ? g_bsum[tid] : 0;
    sm[tid] = v;
    __syncthreads();
#pragma unroll
    for (int d = 1; d < 512; d <<= 1) {
        int t = (tid >= d) ? sm[tid - d] : 0;
        __syncthreads();
        sm[tid] += t;
        __syncthreads();
    }
    if (tid < NSCAN) g_bsum[tid] = sm[tid] - v;   // exclusive
}

__global__ void scan3_kernel() {
    int i = blockIdx.x * blockDim.x + threadIdx.x;
    if (i < NN) {
        int o = g_off[i] + g_bsum[i >> 8];
        g_off[i] = o;
        g_cur[i] = o;
    }
}

__global__ void scatter_kernel(const int* __restrict__ ei) {
    int e = blockIdx.x * blockDim.x + threadIdx.x;
    if (e < EE) {
        int s = __ldg(&ei[e]);
        int d = __ldg(&ei[EE + e]);
        int idx = atomicAdd(&g_cur[d], 1);
        g_srcs[idx] = s;
    }
}

// ---------------- 1. h = x @ W via tf32 mma (tensor pipe) ------------------
// 256 threads = 8 warps, each warp computes a 16x128 tile (m16n8k8 x 16 nt).
// W and x are cvt'd to tf32 once during smem staging. Padded strides kill
// bank conflicts: xs stride 132 words (4g+t distinct), ws stride 136 (8t+g).
#define GM 128                       // nodes per block
#define XSTR 132
#define WSTR 136

__device__ __forceinline__ unsigned f2tf32(float f) {
    unsigned u;
    asm("cvt.rna.tf32.f32 %0, %1;" : "=r"(u) : "f"(f));
    return u;
}
__device__ __forceinline__ float pick4(float a, float b, float c, float d, int t) {
    return t == 0 ? a : (t == 1 ? b : (t == 2 ? c : d));
}

__global__ void gemm_kernel(const float* __restrict__ x,
                            const float* __restrict__ W,
                            const float* __restrict__ att_s,
                            const float* __restrict__ att_d) {
    extern __shared__ unsigned smu[];
    unsigned* ws = smu;                   // 128 * 136 words
    unsigned* xs = smu + DIM * WSTR;      // 128 * 132 words
    const int tid = threadIdx.x;
    const int nb  = blockIdx.x * GM;

    // stage W -> tf32 smem (row k, stride WSTR)
    for (int i = tid * 4; i < DIM * DIM; i += 256 * 4) {
        int k = i >> 7, n = i & 127;
        float4 w = *(const float4*)&W[i];
        uint4 u = make_uint4(f2tf32(w.x), f2tf32(w.y), f2tf32(w.z), f2tf32(w.w));
        *(uint4*)&ws[k * WSTR + n] = u;
    }
    // stage x -> tf32 smem (row node, stride XSTR), zero-fill past NN
    for (int i = tid * 4; i < GM * DIM; i += 256 * 4) {
        int r = i >> 7, c = i & 127;
        uint4 u = make_uint4(0u, 0u, 0u, 0u);
        if (nb + r < NN) {
            float4 v = *(const float4*)&x[(size_t)(nb + r) * DIM + c];
            u = make_uint4(f2tf32(v.x), f2tf32(v.y), f2tf32(v.z), f2tf32(v.w));
        }
        *(uint4*)&xs[r * XSTR + c] = u;
    }
    __syncthreads();

    const int warp = tid >> 5, lane = tid & 31;
    const int g = lane >> 2, t = lane & 3;
    const unsigned* xw = xs + (warp * 16) * XSTR;

    float d[16][4];
#pragma unroll
    for (int nt = 0; nt < 16; nt++)
#pragma unroll
        for (int j = 0; j < 4; j++) d[nt][j] = 0.f;

#pragma unroll
    for (int ks = 0; ks < 16; ks++) {
        const int k0 = ks * 8;
        unsigned a0 = xw[g * XSTR + k0 + t];
        unsigned a1 = xw[(g + 8) * XSTR + k0 + t];
        unsigned a2 = xw[g * XSTR + k0 + t + 4];
        unsigned a3 = xw[(g + 8) * XSTR + k0 + t + 4];
#pragma unroll
        for (int nt = 0; nt < 16; nt++) {
            unsigned b0 = ws[(k0 + t) * WSTR + nt * 8 + g];
            unsigned b1 = ws[(k0 + t + 4) * WSTR + nt * 8 + g];
            asm volatile(
                "mma.sync.aligned.m16n8k8.row.col.f32.tf32.tf32.f32 "
                "{%0,%1,%2,%3}, {%4,%5,%6,%7}, {%8,%9}, {%0,%1,%2,%3};"
                : "+f"(d[nt][0]), "+f"(d[nt][1]), "+f"(d[nt][2]), "+f"(d[nt][3])
                : "r"(a0), "r"(a1), "r"(a2), "r"(a3), "r"(b0), "r"(b1));
        }
    }

    // epilogue: rows row0 = node0+g, row1 = node0+g+8; cols nt*8 + 2t, +1
    const int node0 = nb + warp * 16;
    const int row0 = node0 + g, row1 = node0 + g + 8;

    // attention logit partials per (row, head)
    float ps[2][4], pd[2][4];
#pragma unroll
    for (int r = 0; r < 2; r++)
#pragma unroll
        for (int h = 0; h < 4; h++) { ps[r][h] = 0.f; pd[r][h] = 0.f; }

#pragma unroll
    for (int nt = 0; nt < 16; nt++) {
        const int head = nt >> 2;
        const int cc = ((nt & 3) * 8) + 2 * t;        // col within head
        float2 as = *(const float2*)&att_s[head * CC + cc];
        float2 ad = *(const float2*)&att_d[head * CC + cc];
        ps[0][head] += d[nt][0] * as.x + d[nt][1] * as.y;
        ps[1][head] += d[nt][2] * as.x + d[nt][3] * as.y;
        pd[0][head] += d[nt][0] * ad.x + d[nt][1] * ad.y;
        pd[1][head] += d[nt][2] * ad.x + d[nt][3] * ad.y;
    }
    // reduce across the 4 lanes of each quad (same g, t = 0..3)
#pragma unroll
    for (int r = 0; r < 2; r++)
#pragma unroll
        for (int h = 0; h < 4; h++) {
            ps[r][h] += __shfl_xor_sync(0xffffffffu, ps[r][h], 1);
            ps[r][h] += __shfl_xor_sync(0xffffffffu, ps[r][h], 2);
            pd[r][h] += __shfl_xor_sync(0xffffffffu, pd[r][h], 1);
            pd[r][h] += __shfl_xor_sync(0xffffffffu, pd[r][h], 2);
        }
    // lane t writes head t (avoid dynamic register indexing)
    if (row0 < NN) {
        g_asrc[row0 * HH + t] = pick4(ps[0][0], ps[0][1], ps[0][2], ps[0][3], t);
        g_adst[row0 * HH + t] = pick4(pd[0][0], pd[0][1], pd[0][2], pd[0][3], t);
    }
    if (row1 < NN) {
        g_asrc[row1 * HH + t] = pick4(ps[1][0], ps[1][1], ps[1][2], ps[1][3], t);
        g_adst[row1 * HH + t] = pick4(pd[1][0], pd[1][1], pd[1][2], pd[1][3], t);
    }

    // fp16 h store: h2 col index = (nt*8 + 2t)/2 = nt*4 + t
#pragma unroll
    for (int nt = 0; nt < 16; nt++) {
        if (row0 < NN)
            g_h2[(size_t)row0 * (DIM / 2) + nt * 4 + t] =
                __floats2half2_rn(d[nt][0], d[nt][1]);
        if (row1 < NN)
            g_h2[(size_t)row1 * (DIM / 2) + nt * 4 + t] =
                __floats2half2_rn(d[nt][2], d[nt][3]);
    }
}

// ---------------- 2. gather-aggregate, one warp per dst (no atomics) -------
#define AG_WARPS 8
#define AG_GRID  592
__global__ void agg_kernel(const float* __restrict__ bias) {
    __shared__ float4 s_sum[AG_WARPS * 32];
    __shared__ float4 s_sq [AG_WARPS * 32];
    const int warp = threadIdx.x >> 5, lane = threadIdx.x & 31;
    const int ph = lane & 3;           // head this lane's logit belongs to
    const int pe = lane >> 2;          // edge slot (0..7) this lane scores
    const int myh = lane >> 3;         // head of this lane's 4 columns
    const float4 bv = *(const float4*)&bias[lane * 4];

    float4 csum = make_float4(0.f, 0.f, 0.f, 0.f);
    float4 csq  = make_float4(0.f, 0.f, 0.f, 0.f);

    for (int dst = blockIdx.x * AG_WARPS + warp; dst < NN;
         dst += AG_GRID * AG_WARPS) {
        const float adst_ph = __ldg(&g_adst[dst * HH + ph]);

        // self loop
        float l0 = __ldg(&g_asrc[dst * HH + ph]) + adst_ph;
        l0 = l0 > 0.f ? l0 : NEG_SLOPE * l0;
        float p_self = __expf(l0);
        float s_part = (lane < 4) ? p_self : 0.f;   // one lane per head counts

        uint2 rself = *(const uint2*)&g_h2[(size_t)dst * (DIM / 2) + lane * 2];
        float pw0 = __shfl_sync(0xffffffffu, p_self, myh);
        float2 a0 = __half22float2(*(__half2*)&rself.x);
        float2 a1 = __half22float2(*(__half2*)&rself.y);
        float4 acc = make_float4(a0.x * pw0, a0.y * pw0, a1.x * pw0, a1.y * pw0);

        const int deg = g_deg[dst];
        const int off = g_off[dst];
        for (int c = 0; c < deg; c += 32) {
            const int nc = min(32, deg - c);
            int sv = 0;
            if (lane < nc) sv = __ldg(&g_srcs[off + c + lane]);

#pragma unroll
            for (int h = 0; h < 2; h++) {
                const int e0 = h * 16;
                const int nv = nc - e0;               // valid edges this half
                if (nv <= 0) break;

                float pA = 0.f, pB = 0.f;
                int sA = __shfl_sync(0xffffffffu, sv, e0 + pe);
                int sB = __shfl_sync(0xffffffffu, sv, e0 + pe + 8);
                if (pe < nv) {
                    float ll = __ldg(&g_asrc[sA * HH + ph]) + adst_ph;
                    ll = ll > 0.f ? ll : NEG_SLOPE * ll;
                    pA = __expf(ll);
                }
                if (pe + 8 < nv) {
                    float ll = __ldg(&g_asrc[sB * HH + ph]) + adst_ph;
                    ll = ll > 0.f ? ll : NEG_SLOPE * ll;
                    pB = __expf(ll);
                }
                s_part += pA + pB;

                uint2 raw[16];
#pragma unroll
                for (int e = 0; e < 16; e++) {
                    if (e < nv) {                     // warp-uniform
                        int se = __shfl_sync(0xffffffffu, sv, e0 + e);
                        raw[e] = *(const uint2*)&g_h2[(size_t)se * (DIM / 2) + lane * 2];
                    }
                }
#pragma unroll
                for (int e = 0; e < 16; e++) {
                    if (e < nv) {
                        float pw = (e < 8)
                            ? __shfl_sync(0xffffffffu, pA, e * 4 + myh)
                            : __shfl_sync(0xffffffffu, pB, (e - 8) * 4 + myh);
                        float2 f0 = __half22float2(*(__half2*)&raw[e].x);
                        float2 f1 = __half22float2(*(__half2*)&raw[e].y);
                        acc.x = fmaf(f0.x, pw, acc.x);
                        acc.y = fmaf(f0.y, pw, acc.y);
                        acc.z = fmaf(f1.x, pw, acc.z);
                        acc.w = fmaf(f1.y, pw, acc.w);
                    }
                }
            }
        }

        float st = s_part;
        st += __shfl_xor_sync(0xffffffffu, st, 4);
        st += __shfl_xor_sync(0xffffffffu, st, 8);
        st += __shfl_xor_sync(0xffffffffu, st, 16);
        float r = 1.f / (__shfl_sync(0xffffffffu, st, myh) + 1e-16f);

        float4 v;
        v.x = fmaf(acc.x, r, bv.x);
        v.y = fmaf(acc.y, r, bv.y);
        v.z = fmaf(acc.z, r, bv.z);
        v.w = fmaf(acc.w, r, bv.w);
        *(float4*)&g_acc[(size_t)dst * DIM + lane * 4] = v;

        csum.x += v.x; csum.y += v.y; csum.z += v.z; csum.w += v.w;
        csq.x = fmaf(v.x, v.x, csq.x); csq.y = fmaf(v.y, v.y, csq.y);
        csq.z = fmaf(v.z, v.z, csq.z); csq.w = fmaf(v.w, v.w, csq.w);
    }

    s_sum[warp * 32 + lane] = csum;
    s_sq [warp * 32 + lane] = csq;
    __syncthreads();
    if (warp == 0) {
#pragma unroll
        for (int w = 1; w < AG_WARPS; w++) {
            float4 a = s_sum[w * 32 + lane], b = s_sq[w * 32 + lane];
            csum.x += a.x; csum.y += a.y; csum.z += a.z; csum.w += a.w;
            csq.x  += b.x; csq.y  += b.y; csq.z  += b.z; csq.w  += b.w;
        }
        atomicAdd(&g_colsum[lane * 4 + 0], csum.x);
        atomicAdd(&g_colsum[lane * 4 + 1], csum.y);
        atomicAdd(&g_colsum[lane * 4 + 2], csum.z);
        atomicAdd(&g_colsum[lane * 4 + 3], csum.w);
        atomicAdd(&g_colsq[lane * 4 + 0], csq.x);
        atomicAdd(&g_colsq[lane * 4 + 1], csq.y);
        atomicAdd(&g_colsq[lane * 4 + 2], csq.z);
        atomicAdd(&g_colsq[lane * 4 + 3], csq.w);
    }
}

// ---------------- 3. BN fold + apply + residual + ReLU (bn merged) ---------
__global__ void final_kernel(const float* __restrict__ x,
                             const float* __restrict__ gamma,
                             const float* __restrict__ beta,
                             float* __restrict__ out) {
    int i = blockIdx.x * blockDim.x + threadIdx.x;   // float4 index
    if (i >= NN * DIM / 4) return;
    int cb = (i & 31) * 4;
    float4 cs = *(const float4*)&g_colsum[cb];
    float4 cq = *(const float4*)&g_colsq[cb];
    float4 gm = *(const float4*)&gamma[cb];
    float4 bt = *(const float4*)&beta[cb];
    const float invn = 1.f / NN;
    float mx = cs.x * invn, my = cs.y * invn, mz = cs.z * invn, mw = cs.w * invn;
    float scx = gm.x * rsqrtf(cq.x * invn - mx * mx + BN_EPS);
    float scy = gm.y * rsqrtf(cq.y * invn - my * my + BN_EPS);
    float scz = gm.z * rsqrtf(cq.z * invn - mz * mz + BN_EPS);
    float scw = gm.w * rsqrtf(cq.w * invn - mw * mw + BN_EPS);
    float shx = bt.x - mx * scx, shy = bt.y - my * scy;
    float shz = bt.z - mz * scz, shw = bt.w - mw * scw;

    float4 v  = ((const float4*)g_acc)[i];
    float4 xv = ((const float4*)x)[i];
    float4 o;
    o.x = fmaxf(fmaf(scx, v.x, shx) + xv.x, 0.f);
    o.y = fmaxf(fmaf(scy, v.y, shy) + xv.y, 0.f);
    o.z = fmaxf(fmaf(scz, v.z, shz) + xv.z, 0.f);
    o.w = fmaxf(fmaf(scw, v.w, shw) + xv.w, 0.f);
    ((float4*)out)[i] = o;
}

// ---------------- launch ----------------------------------------------------
extern "C" void kernel_launch(void* const* d_in, const int* in_sizes, int n_in,
                              void* d_out, int out_size) {
    const float* x     = (const float*)d_in[0];
    const int*   ei    = (const int*)d_in[1];      // int32 [2, E]
    const float* W     = (const float*)d_in[2];
    const float* att_s = (const float*)d_in[3];
    const float* att_d = (const float*)d_in[4];
    const float* bias  = (const float*)d_in[5];
    const float* gamma = (const float*)d_in[6];
    const float* beta  = (const float*)d_in[7];
    float*       out   = (float*)d_out;

    const int gemm_smem = (DIM * WSTR + GM * XSTR) * sizeof(unsigned); // ~134 KB
    cudaFuncSetAttribute(gemm_kernel, cudaFuncAttributeMaxDynamicSharedMemorySize,
                         gemm_smem);

    cudaStream_t side;
    cudaStreamCreateWithFlags(&side, cudaStreamNonBlocking);
    cudaEvent_t eFork, eJoin;
    cudaEventCreateWithFlags(&eFork, cudaEventDisableTiming);
    cudaEventCreateWithFlags(&eJoin, cudaEventDisableTiming);

    cudaEventRecord(eFork, 0);
    cudaStreamWaitEvent(side, eFork, 0);

    // CSR build chain on side stream (no dependence on gemm)
    zero_kernel<<<(NN + 255) / 256, 256, 0, side>>>();
    hist_kernel<<<(EE + 255) / 256, 256, 0, side>>>(ei);
    scan1_kernel<<<NSCAN, 256, 0, side>>>();
    scan2_kernel<<<1, 512, 0, side>>>();
    scan3_kernel<<<(NN + 255) / 256, 256, 0, side>>>();
    scatter_kernel<<<(EE + 255) / 256, 256, 0, side>>>(ei);
    cudaEventRecord(eJoin, side);

    // tf32 mma gemm on main stream, concurrent with CSR build
    gemm_kernel<<<(NN + GM - 1) / GM, 256, gemm_smem>>>(x, W, att_s, att_d);

    cudaStreamWaitEvent(0, eJoin, 0);
    agg_kernel<<<AG_GRID, AG_WARPS * 32>>>(bias);
    final_kernel<<<(NN * 32 + 255) / 256, 256>>>(x, gamma, beta, out);
}